// round 4
// baseline (speedup 1.0000x reference)
#include <cuda_runtime.h>
#include <math.h>

#define BB   8
#define NN   128
#define CC   256
#define HID  1024
#define EPSF 1e-5f
#define TILE 32
#define ROWS (BB*NN)          /* 1024  */
#define EDGES (BB*NN*NN)      /* 131072 */
#define PITCH 36              /* floats: 144B rows, 16B aligned */

typedef unsigned long long ull;

// ---------------- scratch (device globals; no allocation anywhere) ---------
__device__ float g_x1[ROWS*CC];
__device__ float g_q [ROWS*CC];
__device__ float g_k [ROWS*CC];
__device__ float g_v [ROWS*CC];
__device__ float g_agg[ROWS*CC];
__device__ float g_attn[EDGES*CC];   // 134 MB
__device__ float g_y2 [EDGES*CC];    // 134 MB

// ---------------- packed f32x2 helpers -------------------------------------
#define FFMA2(c, a, b) \
    asm("fma.rn.f32x2 %0, %1, %2, %3;" : "=l"(c) : "l"(a), "l"(b), "l"(c))

__device__ __forceinline__ ull pack2(float a, float b) {
    ull r;
    asm("mov.b64 %0, {%1, %2};" : "=l"(r)
        : "r"(__float_as_uint(a)), "r"(__float_as_uint(b)));
    return r;
}
__device__ __forceinline__ void unpack2(ull p, float& a, float& b) {
    unsigned lo, hi;
    asm("mov.b64 {%0, %1}, %2;" : "=r"(lo), "=r"(hi) : "l"(p));
    a = __uint_as_float(lo); b = __uint_as_float(hi);
}

__device__ __forceinline__ float warpSum(float v) {
#pragma unroll
    for (int o = 16; o > 0; o >>= 1) v += __shfl_xor_sync(0xffffffffu, v, o);
    return v;
}

__device__ __forceinline__ float blockSum(float v, float* sred, int t) {
    v = warpSum(v);
    __syncthreads();
    if ((t & 31) == 0) sred[t >> 5] = v;
    __syncthreads();
    float tot = 0.f;
#pragma unroll
    for (int w = 0; w < 8; w++) tot += sred[w];
    return tot;
}

// =================== K1: LN1 + q,k,v projections (per node row) ============
__global__ void __launch_bounds__(256) k1_node_qkv(
    const float* __restrict__ x,
    const float* __restrict__ Wq, const float* __restrict__ bq,
    const float* __restrict__ Wk, const float* __restrict__ bk,
    const float* __restrict__ Wv, const float* __restrict__ bv,
    const float* __restrict__ ln1_s, const float* __restrict__ ln1_b)
{
    __shared__ __align__(16) float sx[CC];
    __shared__ float sred[8];
    int r = blockIdx.x, t = threadIdx.x;

    float xv = x[r*CC + t];
    float mean = blockSum(xv, sred, t) * (1.f/CC);
    float d = xv - mean;
    float var = blockSum(d*d, sred, t) * (1.f/CC);
    float rs = rsqrtf(var + EPSF);
    float x1 = d * rs * ln1_s[t] + ln1_b[t];
    sx[t] = x1;
    g_x1[r*CC + t] = x1;
    __syncthreads();

    float aq = bq[t], ak = bk[t], av = bv[t];
    const float4* sx4 = (const float4*)sx;
#pragma unroll 1
    for (int k4 = 0; k4 < CC/4; k4++) {
        float4 xv4 = sx4[k4];
        int kk = 4*k4;
        aq = fmaf(xv4.x, Wq[(kk+0)*CC+t], aq);
        aq = fmaf(xv4.y, Wq[(kk+1)*CC+t], aq);
        aq = fmaf(xv4.z, Wq[(kk+2)*CC+t], aq);
        aq = fmaf(xv4.w, Wq[(kk+3)*CC+t], aq);
        ak = fmaf(xv4.x, Wk[(kk+0)*CC+t], ak);
        ak = fmaf(xv4.y, Wk[(kk+1)*CC+t], ak);
        ak = fmaf(xv4.z, Wk[(kk+2)*CC+t], ak);
        ak = fmaf(xv4.w, Wk[(kk+3)*CC+t], ak);
        av = fmaf(xv4.x, Wv[(kk+0)*CC+t], av);
        av = fmaf(xv4.y, Wv[(kk+1)*CC+t], av);
        av = fmaf(xv4.z, Wv[(kk+2)*CC+t], av);
        av = fmaf(xv4.w, Wv[(kk+3)*CC+t], av);
    }
    g_q[r*CC+t] = aq;  g_k[r*CC+t] = ak;  g_v[r*CC+t] = av;
}

// =================== K2: e = y@We+be ; attn = (q*k/sqrt(dk))*(e+1)*e =======
// smem: sp[k][r] transposed tile (CC x PITCH floats = 36 KB, dynamic)
__global__ void __launch_bounds__(256) k2_edge_attn(
    const float* __restrict__ y,
    const float* __restrict__ We, const float* __restrict__ be)
{
    extern __shared__ __align__(16) float sp[];
    int base = blockIdx.x * TILE;
    int t = threadIdx.x;
    int ri = base / NN;
    int b  = ri >> 7;
    int j0 = base & (NN - 1);

#pragma unroll
    for (int r = 0; r < TILE; r++)
        sp[t*PITCH + r] = y[(size_t)(base + r)*CC + t];
    __syncthreads();

    ull acc[TILE/2];
    {
        float bev = be[t];
        ull bp = pack2(bev, bev);
#pragma unroll
        for (int i = 0; i < TILE/2; i++) acc[i] = bp;
    }

#pragma unroll 4
    for (int k = 0; k < CC; k++) {
        float w = We[k*CC + t];
        ull wp = pack2(w, w);
        const ulonglong2* row = (const ulonglong2*)(sp + k*PITCH);
#pragma unroll
        for (int q = 0; q < 8; q++) {
            ulonglong2 v = row[q];
            FFMA2(acc[2*q],   v.x, wp);
            FFMA2(acc[2*q+1], v.y, wp);
        }
    }

    float qv = g_q[ri*CC + t] * 0.17677669529663687f;  // 1/sqrt(32)
    int krow = (b << 7) + j0;
#pragma unroll
    for (int i = 0; i < TILE/2; i++) {
        float e0, e1;
        unpack2(acc[i], e0, e1);
        int r0 = 2*i, r1 = 2*i + 1;
        float kv0 = g_k[(krow + r0)*CC + t];
        float kv1 = g_k[(krow + r1)*CC + t];
        g_attn[(size_t)(base + r0)*CC + t] = qv * kv0 * (e0 + 1.f) * e0;
        g_attn[(size_t)(base + r1)*CC + t] = qv * kv1 * (e1 + 1.f) * e1;
    }
}

// =================== K3: edge_out = attn@Woe+boe ; y2 = LN4(edge_out + y) ==
#define LNP 257
__global__ void __launch_bounds__(256) k3_edgeout_ln(
    const float* __restrict__ y,
    const float* __restrict__ Woe, const float* __restrict__ boe,
    const float* __restrict__ ln4_s, const float* __restrict__ ln4_b)
{
    extern __shared__ __align__(16) float sp[];
    int base = blockIdx.x * TILE;
    int t = threadIdx.x;

#pragma unroll
    for (int r = 0; r < TILE; r++)
        sp[t*PITCH + r] = g_attn[(size_t)(base + r)*CC + t];
    __syncthreads();

    ull acc[TILE/2];
    {
        float bv = boe[t];
        ull bp = pack2(bv, bv);
#pragma unroll
        for (int i = 0; i < TILE/2; i++) acc[i] = bp;
    }

#pragma unroll 4
    for (int k = 0; k < CC; k++) {
        float w = Woe[k*CC + t];
        ull wp = pack2(w, w);
        const ulonglong2* row = (const ulonglong2*)(sp + k*PITCH);
#pragma unroll
        for (int q = 0; q < 8; q++) {
            ulonglong2 v = row[q];
            FFMA2(acc[2*q],   v.x, wp);
            FFMA2(acc[2*q+1], v.y, wp);
        }
    }
    __syncthreads();                 // done reading sp; reuse as LN buffer

    float* ln = sp;                  // [TILE][LNP]
#pragma unroll
    for (int i = 0; i < TILE/2; i++) {
        float e0, e1;
        unpack2(acc[i], e0, e1);
        int r0 = 2*i, r1 = 2*i + 1;
        ln[r0*LNP + t] = e0 + y[(size_t)(base + r0)*CC + t];
        ln[r1*LNP + t] = e1 + y[(size_t)(base + r1)*CC + t];
    }
    __syncthreads();

    int w = t >> 5, l = t & 31;
#pragma unroll
    for (int u = 0; u < 4; u++) {
        int r = (u << 3) + w;
        float s = 0.f, sq = 0.f;
#pragma unroll
        for (int c0 = 0; c0 < CC; c0 += 32) {
            float v = ln[r*LNP + c0 + l];
            s += v; sq = fmaf(v, v, sq);
        }
        s = warpSum(s); sq = warpSum(sq);
        float m  = s * (1.f/CC);
        float rs = rsqrtf(sq * (1.f/CC) - m*m + EPSF);
#pragma unroll
        for (int c0 = 0; c0 < CC; c0 += 32) {
            int c = c0 + l;
            g_y2[(size_t)(base + r)*CC + c] =
                (ln[r*LNP + c] - m) * rs * ln4_s[c] + ln4_b[c];
        }
    }
}

// =================== K4: softmax over j (per channel) + V aggregation ======
__global__ void __launch_bounds__(256) k4_softmax_agg()
{
    int ri = blockIdx.x;
    int b  = ri >> 7;
    int c  = threadIdx.x;
    const float* ap = g_attn + (size_t)ri * NN * CC + c;
    const float* vp = g_v    + (size_t)(b << 7) * CC + c;

    float m = -3.4e38f, s = 0.f, acc = 0.f;
#pragma unroll 4
    for (int j = 0; j < NN; j++) {
        float a    = ap[(size_t)j * CC];
        float nm   = fmaxf(m, a);
        float corr = __expf(m - nm);
        float p    = __expf(a - nm);
        s   = s   * corr + p;
        acc = acc * corr + p * vp[(size_t)j * CC];
        m = nm;
    }
    g_agg[ri*CC + c] = acc / s;
}

// =================== K5: node out proj + LN3 + node MLP + LN5 ==============
__global__ void __launch_bounds__(256) k5_node_mlp(
    const float* __restrict__ Won, const float* __restrict__ bon,
    const float* __restrict__ w1, const float* __restrict__ b1,
    const float* __restrict__ w2, const float* __restrict__ b2,
    const float* __restrict__ ln3_s, const float* __restrict__ ln3_b,
    const float* __restrict__ ln5_s, const float* __restrict__ ln5_b,
    float* __restrict__ xout)
{
    __shared__ __align__(16) float sagg[CC];
    __shared__ __align__(16) float sx2[CC];
    __shared__ __align__(16) float shid[HID];
    __shared__ float sred[8];
    int r = blockIdx.x, t = threadIdx.x;

    sagg[t] = g_agg[r*CC + t];
    __syncthreads();

    float no = bon[t];
    const float4* sa4 = (const float4*)sagg;
#pragma unroll 1
    for (int k4 = 0; k4 < CC/4; k4++) {
        float4 av = sa4[k4]; int kk = 4*k4;
        no = fmaf(av.x, Won[(kk+0)*CC+t], no);
        no = fmaf(av.y, Won[(kk+1)*CC+t], no);
        no = fmaf(av.z, Won[(kk+2)*CC+t], no);
        no = fmaf(av.w, Won[(kk+3)*CC+t], no);
    }
    float pre = g_x1[r*CC + t] + no;

    float mean = blockSum(pre, sred, t) * (1.f/CC);
    float d = pre - mean;
    float var = blockSum(d*d, sred, t) * (1.f/CC);
    float x2 = d * rsqrtf(var + EPSF) * ln3_s[t] + ln3_b[t];
    sx2[t] = x2;
    __syncthreads();

    const float4* sx24 = (const float4*)sx2;
#pragma unroll 1
    for (int hb = 0; hb < 4; hb++) {
        int h = hb*CC + t;
        float a = b1[h];
#pragma unroll 1
        for (int k4 = 0; k4 < CC/4; k4++) {
            float4 xv = sx24[k4]; int kk = 4*k4;
            a = fmaf(xv.x, w1[(kk+0)*HID+h], a);
            a = fmaf(xv.y, w1[(kk+1)*HID+h], a);
            a = fmaf(xv.z, w1[(kk+2)*HID+h], a);
            a = fmaf(xv.w, w1[(kk+3)*HID+h], a);
        }
        shid[h] = fmaxf(a, 0.f);
    }
    __syncthreads();

    float o = b2[t];
    const float4* sh4 = (const float4*)shid;
#pragma unroll 1
    for (int k4 = 0; k4 < HID/4; k4++) {
        float4 hv = sh4[k4]; int kk = 4*k4;
        o = fmaf(hv.x, w2[(kk+0)*CC+t], o);
        o = fmaf(hv.y, w2[(kk+1)*CC+t], o);
        o = fmaf(hv.z, w2[(kk+2)*CC+t], o);
        o = fmaf(hv.w, w2[(kk+3)*CC+t], o);
    }
    float pre2 = x2 + o;
    float mean2 = blockSum(pre2, sred, t) * (1.f/CC);
    float d2 = pre2 - mean2;
    float var2 = blockSum(d2*d2, sred, t) * (1.f/CC);
    xout[r*CC + t] = d2 * rsqrtf(var2 + EPSF) * ln5_s[t] + ln5_b[t];
}

// =================== K6: edge MLP + LN6 (f32x2, transposed staging) ========
// dynamic smem: sy = [CC][PITCH] (36 KB), sh = [CC][PITCH] (36 KB)
__global__ void __launch_bounds__(256) k6_edge_mlp(
    const float* __restrict__ w1, const float* __restrict__ b1,
    const float* __restrict__ w2, const float* __restrict__ b2,
    const float* __restrict__ ln6_s, const float* __restrict__ ln6_b,
    float* __restrict__ yout)
{
    extern __shared__ __align__(16) float dsm[];
    float* sy = dsm;                  // CC*PITCH floats
    float* sh = dsm + CC*PITCH;       // CC*PITCH floats
    int base = blockIdx.x * TILE, t = threadIdx.x;

#pragma unroll
    for (int r = 0; r < TILE; r++)
        sy[t*PITCH + r] = g_y2[(size_t)(base + r)*CC + t];

    ull oacc[TILE/2];
#pragma unroll
    for (int i = 0; i < TILE/2; i++) oacc[i] = 0ull;
    __syncthreads();

#pragma unroll 1
    for (int ch = 0; ch < 4; ch++) {
        int h = ch*CC + t;
        ull hacc[TILE/2];
        {
            float hb = b1[h];
            ull hp = pack2(hb, hb);
#pragma unroll
            for (int i = 0; i < TILE/2; i++) hacc[i] = hp;
        }

#pragma unroll 4
        for (int k = 0; k < CC; k++) {
            float w = w1[k*HID + h];
            ull wp = pack2(w, w);
            const ulonglong2* row = (const ulonglong2*)(sy + k*PITCH);
#pragma unroll
            for (int q = 0; q < 8; q++) {
                ulonglong2 v = row[q];
                FFMA2(hacc[2*q],   v.x, wp);
                FFMA2(hacc[2*q+1], v.y, wp);
            }
        }
        __syncthreads();              // prior chunk's sh reads done
#pragma unroll
        for (int i = 0; i < TILE/2; i++) {
            float e0, e1;
            unpack2(hacc[i], e0, e1);
            sh[t*PITCH + 2*i]     = fmaxf(e0, 0.f);
            sh[t*PITCH + 2*i + 1] = fmaxf(e1, 0.f);
        }
        __syncthreads();

#pragma unroll 4
        for (int k = 0; k < CC; k++) {
            float w = w2[(ch*CC + k)*CC + t];
            ull wp = pack2(w, w);
            const ulonglong2* row = (const ulonglong2*)(sh + k*PITCH);
#pragma unroll
            for (int q = 0; q < 8; q++) {
                ulonglong2 v = row[q];
                FFMA2(oacc[2*q],   v.x, wp);
                FFMA2(oacc[2*q+1], v.y, wp);
            }
        }
    }

    __syncthreads();                  // sh free; reuse as LN buffer
    float* ln = sh;                   // [TILE][LNP]
    {
        float b2v = b2[t];
#pragma unroll
        for (int i = 0; i < TILE/2; i++) {
            float e0, e1;
            unpack2(oacc[i], e0, e1);
            int r0 = 2*i, r1 = 2*i + 1;
            ln[r0*LNP + t] = e0 + b2v + sy[t*PITCH + r0];
            ln[r1*LNP + t] = e1 + b2v + sy[t*PITCH + r1];
        }
    }
    __syncthreads();

    int w = t >> 5, l = t & 31;
#pragma unroll
    for (int u = 0; u < 4; u++) {
        int r = (u << 3) + w;
        float s = 0.f, sq = 0.f;
#pragma unroll
        for (int c0 = 0; c0 < CC; c0 += 32) {
            float v = ln[r*LNP + c0 + l];
            s += v; sq = fmaf(v, v, sq);
        }
        s = warpSum(s); sq = warpSum(sq);
        float m  = s * (1.f/CC);
        float rs = rsqrtf(sq * (1.f/CC) - m*m + EPSF);
#pragma unroll
        for (int c0 = 0; c0 < CC; c0 += 32) {
            int c = c0 + l;
            yout[(size_t)(base + r)*CC + c] =
                (ln[r*LNP + c] - m) * rs * ln6_s[c] + ln6_b[c];
        }
    }
}

// =================== launch ================================================
extern "C" void kernel_launch(void* const* d_in, const int* in_sizes, int n_in,
                              void* d_out, int out_size)
{
    const float* x   = (const float*)d_in[0];
    const float* y   = (const float*)d_in[1];
    const float* Wq  = (const float*)d_in[2];
    const float* bq  = (const float*)d_in[3];
    const float* Wk  = (const float*)d_in[4];
    const float* bk  = (const float*)d_in[5];
    const float* Wv  = (const float*)d_in[6];
    const float* bv  = (const float*)d_in[7];
    const float* We  = (const float*)d_in[8];
    const float* be  = (const float*)d_in[9];
    const float* Woe = (const float*)d_in[10];
    const float* boe = (const float*)d_in[11];
    const float* Won = (const float*)d_in[12];
    const float* bon = (const float*)d_in[13];
    const float* m1w1 = (const float*)d_in[14];
    const float* m1b1 = (const float*)d_in[15];
    const float* m1w2 = (const float*)d_in[16];
    const float* m1b2 = (const float*)d_in[17];
    const float* m2w1 = (const float*)d_in[18];
    const float* m2b1 = (const float*)d_in[19];
    const float* m2w2 = (const float*)d_in[20];
    const float* m2b2 = (const float*)d_in[21];
    const float* ln1s = (const float*)d_in[22];
    const float* ln1b = (const float*)d_in[23];
    const float* ln3s = (const float*)d_in[24];
    const float* ln3b = (const float*)d_in[25];
    const float* ln4s = (const float*)d_in[26];
    const float* ln4b = (const float*)d_in[27];
    const float* ln5s = (const float*)d_in[28];
    const float* ln5b = (const float*)d_in[29];
    const float* ln6s = (const float*)d_in[30];
    const float* ln6b = (const float*)d_in[31];

    float* xout = (float*)d_out;                   // (8,128,256)
    float* yout = (float*)d_out + ROWS*CC;         // (8,128,128,256)

    const int smem1 = CC*PITCH*sizeof(float);      // 36 KB
    const int smem2 = 2*CC*PITCH*sizeof(float);    // 72 KB
    cudaFuncSetAttribute(k2_edge_attn,
                         cudaFuncAttributeMaxDynamicSharedMemorySize, smem1);
    cudaFuncSetAttribute(k3_edgeout_ln,
                         cudaFuncAttributeMaxDynamicSharedMemorySize, smem1);
    cudaFuncSetAttribute(k6_edge_mlp,
                         cudaFuncAttributeMaxDynamicSharedMemorySize, smem2);

    k1_node_qkv<<<ROWS, 256>>>(x, Wq, bq, Wk, bk, Wv, bv, ln1s, ln1b);
    k2_edge_attn<<<EDGES/TILE, 256, smem1>>>(y, We, be);
    k3_edgeout_ln<<<EDGES/TILE, 256, smem1>>>(y, Woe, boe, ln4s, ln4b);
    k4_softmax_agg<<<ROWS, 256>>>();
    k5_node_mlp<<<ROWS, 256>>>(Won, bon, m1w1, m1b1, m1w2, m1b2,
                               ln3s, ln3b, ln5s, ln5b, xout);
    k6_edge_mlp<<<EDGES/TILE, 256, smem2>>>(
        m2w1, m2b1, m2w2, m2b2, ln6s, ln6b, yout);
}

// round 9
// speedup vs baseline: 2.7755x; 2.7755x over previous
#include <cuda_runtime.h>
#include <math.h>
#include <stdint.h>

#define BB   8
#define NN   128
#define CC   256
#define HID  1024
#define EPSF 1e-5f
#define ROWS (BB*NN)          /* 1024  */
#define EDGES (BB*NN*NN)      /* 131072 */
#define PA   260              /* A smem pitch in floats */
#define PB   68               /* B smem pitch in floats */

// ---------------- scratch (device globals; no allocation anywhere) ---------
__device__ float g_x1[ROWS*CC];
__device__ float g_q [ROWS*CC];
__device__ float g_k [ROWS*CC];
__device__ float g_v [ROWS*CC];
__device__ float g_agg[ROWS*CC];
__device__ float g_attn[(size_t)EDGES*CC];    // 134 MB
__device__ float g_y2 [(size_t)EDGES*CC];     // 134 MB
__device__ float g_hid[(size_t)EDGES*HID];    // 512 MB
__device__ float g_WeT [CC*CC];               // [n][k]
__device__ float g_WoeT[CC*CC];
__device__ float g_w1T [HID*CC];              // [h][k]
__device__ float g_w2T [CC*HID];              // [n][k]

// ---------------- mma.sync tf32 helpers ------------------------------------
__device__ __forceinline__ uint32_t f2tf(float f) {
    uint32_t r;
    asm("cvt.rna.tf32.f32 %0, %1;" : "=r"(r) : "f"(f));
    return r;
}
__device__ __forceinline__ void mma8(float* c, const uint32_t a[4],
                                     uint32_t b0, uint32_t b1) {
    asm volatile("mma.sync.aligned.m16n8k8.row.col.f32.tf32.tf32.f32 "
        "{%0,%1,%2,%3}, {%4,%5,%6,%7}, {%8,%9}, {%0,%1,%2,%3};"
        : "+f"(c[0]), "+f"(c[1]), "+f"(c[2]), "+f"(c[3])
        : "r"(a[0]), "r"(a[1]), "r"(a[2]), "r"(a[3]), "r"(b0), "r"(b1));
}

// stage A tile (128 x 256 floats) -> smem tf32, pitch PA. 512 threads.
__device__ __forceinline__ void stageA(uint32_t* __restrict__ sA,
                                       const float* __restrict__ src,
                                       size_t row0, int ld, int k0, int t) {
#pragma unroll
    for (int i = 0; i < 16; i++) {
        int f = t + 512 * i;
        int m = f >> 6, k = (f & 63) * 4;
        float4 v = *(const float4*)(src + (row0 + m) * (size_t)ld + k0 + k);
        uint4 u;
        u.x = f2tf(v.x); u.y = f2tf(v.y); u.z = f2tf(v.z); u.w = f2tf(v.w);
        *(uint4*)(sA + m * PA + k) = u;
    }
}
// stage B chunk (256 n x 64 k floats) -> smem tf32, pitch PB. 512 threads.
__device__ __forceinline__ void stageB(uint32_t* __restrict__ sB,
                                       const float* __restrict__ W,
                                       int ld, int k0, int t) {
#pragma unroll
    for (int i = 0; i < 8; i++) {
        int f = t + 512 * i;
        int n = f >> 4, k = (f & 15) * 4;
        float4 v = *(const float4*)(W + (size_t)n * ld + k0 + k);
        uint4 u;
        u.x = f2tf(v.x); u.y = f2tf(v.y); u.z = f2tf(v.z); u.w = f2tf(v.w);
        *(uint4*)(sB + n * PB + k) = u;
    }
}
// one K=64 chunk of MMAs. Pass sA pre-offset to the K-chunk's first column.
__device__ __forceinline__ void gemm64(const uint32_t* __restrict__ sA,
                                       const uint32_t* __restrict__ sB,
                                       float acc[2][8][4],
                                       int m0, int n0, int g, int tig) {
#pragma unroll
    for (int ks = 0; ks < 8; ks++) {
        int k0 = ks * 8;
        uint32_t af[2][4];
#pragma unroll
        for (int mf = 0; mf < 2; mf++) {
            int r = m0 + mf * 16 + g;
            af[mf][0] = sA[r * PA + k0 + tig];
            af[mf][1] = sA[(r + 8) * PA + k0 + tig];
            af[mf][2] = sA[r * PA + k0 + tig + 4];
            af[mf][3] = sA[(r + 8) * PA + k0 + tig + 4];
        }
#pragma unroll
        for (int nf = 0; nf < 8; nf++) {
            int n = n0 + nf * 8 + g;
            uint32_t b0 = sB[n * PB + k0 + tig];
            uint32_t b1 = sB[n * PB + k0 + tig + 4];
            mma8(acc[0][nf], af[0], b0, b1);
            mma8(acc[1][nf], af[1], b0, b1);
        }
    }
}
__device__ __forceinline__ void initacc(float acc[2][8][4],
                                        const float* sbias, int n0, int tig) {
#pragma unroll
    for (int mf = 0; mf < 2; mf++)
#pragma unroll
        for (int nf = 0; nf < 8; nf++) {
            int c = n0 + nf * 8 + 2 * tig;
            acc[mf][nf][0] = acc[mf][nf][2] = sbias[c];
            acc[mf][nf][1] = acc[mf][nf][3] = sbias[c + 1];
        }
}

// ---------------- misc fp32 helpers ----------------------------------------
__device__ __forceinline__ float warpSum(float v) {
#pragma unroll
    for (int o = 16; o > 0; o >>= 1) v += __shfl_xor_sync(0xffffffffu, v, o);
    return v;
}
__device__ __forceinline__ float blockSum(float v, float* sred, int t) {
    v = warpSum(v);
    __syncthreads();
    if ((t & 31) == 0) sred[t >> 5] = v;
    __syncthreads();
    float tot = 0.f;
#pragma unroll
    for (int w = 0; w < 8; w++) tot += sred[w];
    return tot;
}
// LN over 128 rows x 256 cols in ln[r*PA + c] (512 threads)
__device__ __forceinline__ void ln_rows128(const float* ln, float* __restrict__ out,
                                           size_t base, const float* __restrict__ s,
                                           const float* __restrict__ bsh, int t) {
    int w = t >> 5, l = t & 31;
#pragma unroll 1
    for (int u = 0; u < 8; u++) {
        int r = u * 16 + w;
        float sm = 0.f, sq = 0.f;
#pragma unroll
        for (int c0 = 0; c0 < CC; c0 += 32) {
            float v = ln[r * PA + c0 + l];
            sm += v; sq = fmaf(v, v, sq);
        }
        sm = warpSum(sm); sq = warpSum(sq);
        float mean = sm * (1.f / CC);
        float rstd = rsqrtf(sq * (1.f / CC) - mean * mean + EPSF);
#pragma unroll
        for (int c0 = 0; c0 < CC; c0 += 32) {
            int c = c0 + l;
            out[(base + r) * CC + c] = (ln[r * PA + c] - mean) * rstd * s[c] + bsh[c];
        }
    }
}

// ---------------- weight transpose -----------------------------------------
__global__ void ktrans(const float* __restrict__ src, int R, int Cc, int which) {
    float* dst = which == 0 ? g_WeT : which == 1 ? g_WoeT
               : which == 2 ? g_w1T : g_w2T;
    __shared__ float tb[32][33];
    int bx = blockIdx.x * 32, by = blockIdx.y * 32;
    int tx = threadIdx.x, ty = threadIdx.y;
#pragma unroll
    for (int i = 0; i < 32; i += 8)
        tb[ty + i][tx] = src[(size_t)(by + ty + i) * Cc + bx + tx];
    __syncthreads();
#pragma unroll
    for (int i = 0; i < 32; i += 8)
        dst[(size_t)(bx + ty + i) * R + by + tx] = tb[tx][ty + i];
}

// ---------------- K1: LN1 + qkv --------------------------------------------
__global__ void __launch_bounds__(256) k1_node_qkv(
    const float* __restrict__ x,
    const float* __restrict__ Wq, const float* __restrict__ bq,
    const float* __restrict__ Wk, const float* __restrict__ bk,
    const float* __restrict__ Wv, const float* __restrict__ bv,
    const float* __restrict__ ln1_s, const float* __restrict__ ln1_b)
{
    __shared__ __align__(16) float sx[CC];
    __shared__ float sred[8];
    int r = blockIdx.x, t = threadIdx.x;

    float xv = x[r*CC + t];
    float mean = blockSum(xv, sred, t) * (1.f/CC);
    float d = xv - mean;
    float var = blockSum(d*d, sred, t) * (1.f/CC);
    float x1 = d * rsqrtf(var + EPSF) * ln1_s[t] + ln1_b[t];
    sx[t] = x1;
    g_x1[r*CC + t] = x1;
    __syncthreads();

    float aq = bq[t], ak = bk[t], av = bv[t];
    const float4* sx4 = (const float4*)sx;
#pragma unroll 1
    for (int k4 = 0; k4 < CC/4; k4++) {
        float4 v = sx4[k4]; int kk = 4*k4;
        aq = fmaf(v.x, Wq[(kk+0)*CC+t], aq);
        aq = fmaf(v.y, Wq[(kk+1)*CC+t], aq);
        aq = fmaf(v.z, Wq[(kk+2)*CC+t], aq);
        aq = fmaf(v.w, Wq[(kk+3)*CC+t], aq);
        ak = fmaf(v.x, Wk[(kk+0)*CC+t], ak);
        ak = fmaf(v.y, Wk[(kk+1)*CC+t], ak);
        ak = fmaf(v.z, Wk[(kk+2)*CC+t], ak);
        ak = fmaf(v.w, Wk[(kk+3)*CC+t], ak);
        av = fmaf(v.x, Wv[(kk+0)*CC+t], av);
        av = fmaf(v.y, Wv[(kk+1)*CC+t], av);
        av = fmaf(v.z, Wv[(kk+2)*CC+t], av);
        av = fmaf(v.w, Wv[(kk+3)*CC+t], av);
    }
    g_q[r*CC+t] = aq;  g_k[r*CC+t] = ak;  g_v[r*CC+t] = av;
}

#define DSMEM ((128*PA + 256*PB) * 4)   /* 202,752 B */

// ---------------- K2: e-proj MMA + attn epilogue ---------------------------
__global__ void __launch_bounds__(512, 1) k2g(
    const float* __restrict__ y, const float* __restrict__ be)
{
    extern __shared__ __align__(16) char dsm[];
    uint32_t* sA = (uint32_t*)dsm;
    uint32_t* sB = sA + 128 * PA;
    __shared__ float s_q[CC], s_bb[CC];

    int t = threadIdx.x, lane = t & 31, wid = t >> 5;
    int m0 = (wid & 3) * 32, n0 = (wid >> 2) * 64;
    int g = lane >> 2, tig = lane & 3;
    int tile = blockIdx.x;
    size_t base = (size_t)tile * 128;
    int krow = (tile >> 7) << 7;

    if (t < CC) {
        s_bb[t] = be[t];
        s_q[t]  = g_q[(size_t)tile*CC + t] * 0.17677669529663687f;  // 1/sqrt(32)
    }
    stageA(sA, y, base, CC, 0, t);
    __syncthreads();

    float acc[2][8][4];
    initacc(acc, s_bb, n0, tig);
#pragma unroll 1
    for (int kc = 0; kc < 4; kc++) {
        stageB(sB, g_WeT, CC, kc * 64, t);
        __syncthreads();
        gemm64(sA + kc * 64, sB, acc, m0, n0, g, tig);
        __syncthreads();
    }

#pragma unroll
    for (int mf = 0; mf < 2; mf++)
#pragma unroll
        for (int nf = 0; nf < 8; nf++) {
            int r = m0 + mf * 16 + g;
            int c = n0 + nf * 8 + 2 * tig;
#pragma unroll
            for (int h = 0; h < 2; h++) {
                int rr = r + 8 * h;
                float e0 = acc[mf][nf][2*h], e1 = acc[mf][nf][2*h+1];
                float2 kv = *(const float2*)(g_k + (size_t)(krow + rr) * CC + c);
                float2 o;
                o.x = s_q[c]   * kv.x * (e0 + 1.f) * e0;
                o.y = s_q[c+1] * kv.y * (e1 + 1.f) * e1;
                *(float2*)(g_attn + (base + rr) * CC + c) = o;
            }
        }
}

// ---------------- K3: edge_out MMA + LN4 -----------------------------------
__global__ void __launch_bounds__(512, 1) k3g(
    const float* __restrict__ y, const float* __restrict__ boe,
    const float* __restrict__ ln4_s, const float* __restrict__ ln4_b)
{
    extern __shared__ __align__(16) char dsm[];
    uint32_t* sA = (uint32_t*)dsm;
    uint32_t* sB = sA + 128 * PA;
    float* ln = (float*)dsm;
    __shared__ float s_bb[CC];

    int t = threadIdx.x, lane = t & 31, wid = t >> 5;
    int m0 = (wid & 3) * 32, n0 = (wid >> 2) * 64;
    int g = lane >> 2, tig = lane & 3;
    int tile = blockIdx.x;
    size_t base = (size_t)tile * 128;

    if (t < CC) s_bb[t] = boe[t];
    stageA(sA, g_attn, base, CC, 0, t);
    __syncthreads();

    float acc[2][8][4];
    initacc(acc, s_bb, n0, tig);
#pragma unroll 1
    for (int kc = 0; kc < 4; kc++) {
        stageB(sB, g_WoeT, CC, kc * 64, t);
        __syncthreads();
        gemm64(sA + kc * 64, sB, acc, m0, n0, g, tig);
        __syncthreads();
    }

    // overwrite A region with residual-added rows for LN
#pragma unroll
    for (int mf = 0; mf < 2; mf++)
#pragma unroll
        for (int nf = 0; nf < 8; nf++) {
            int r = m0 + mf * 16 + g;
            int c = n0 + nf * 8 + 2 * tig;
#pragma unroll
            for (int h = 0; h < 2; h++) {
                int rr = r + 8 * h;
                float2 yv = *(const float2*)(y + (base + rr) * CC + c);
                float2 o;
                o.x = acc[mf][nf][2*h]   + yv.x;
                o.y = acc[mf][nf][2*h+1] + yv.y;
                *(float2*)(ln + rr * PA + c) = o;
            }
        }
    __syncthreads();

    ln_rows128(ln, g_y2, base, ln4_s, ln4_b, t);
}

// ---------------- K4: softmax over j + V aggregation -----------------------
__global__ void __launch_bounds__(256) k4_softmax_agg()
{
    int ri = blockIdx.x;
    int b  = ri >> 7;
    int c  = threadIdx.x;
    const float* ap = g_attn + (size_t)ri * NN * CC + c;
    const float* vp = g_v    + (size_t)(b << 7) * CC + c;

    float m = -3.4e38f, s = 0.f, acc = 0.f;
#pragma unroll 4
    for (int j = 0; j < NN; j++) {
        float a    = ap[(size_t)j * CC];
        float nm   = fmaxf(m, a);
        float corr = __expf(m - nm);
        float p    = __expf(a - nm);
        s   = s   * corr + p;
        acc = acc * corr + p * vp[(size_t)j * CC];
        m = nm;
    }
    g_agg[ri*CC + c] = acc / s;
}

// ---------------- K5: node out proj + LN3 + MLP + LN5 ----------------------
__global__ void __launch_bounds__(256) k5_node_mlp(
    const float* __restrict__ Won, const float* __restrict__ bon,
    const float* __restrict__ w1, const float* __restrict__ b1,
    const float* __restrict__ w2, const float* __restrict__ b2,
    const float* __restrict__ ln3_s, const float* __restrict__ ln3_b,
    const float* __restrict__ ln5_s, const float* __restrict__ ln5_b,
    float* __restrict__ xout)
{
    __shared__ __align__(16) float sagg[CC];
    __shared__ __align__(16) float sx2[CC];
    __shared__ __align__(16) float shid[HID];
    __shared__ float sred[8];
    int r = blockIdx.x, t = threadIdx.x;

    sagg[t] = g_agg[r*CC + t];
    __syncthreads();

    float no = bon[t];
    const float4* sa4 = (const float4*)sagg;
#pragma unroll 1
    for (int k4 = 0; k4 < CC/4; k4++) {
        float4 av = sa4[k4]; int kk = 4*k4;
        no = fmaf(av.x, Won[(kk+0)*CC+t], no);
        no = fmaf(av.y, Won[(kk+1)*CC+t], no);
        no = fmaf(av.z, Won[(kk+2)*CC+t], no);
        no = fmaf(av.w, Won[(kk+3)*CC+t], no);
    }
    float pre = g_x1[r*CC + t] + no;

    float mean = blockSum(pre, sred, t) * (1.f/CC);
    float d = pre - mean;
    float var = blockSum(d*d, sred, t) * (1.f/CC);
    float x2 = d * rsqrtf(var + EPSF) * ln3_s[t] + ln3_b[t];
    sx2[t] = x2;
    __syncthreads();

    const float4* sx24 = (const float4*)sx2;
#pragma unroll 1
    for (int hb = 0; hb < 4; hb++) {
        int h = hb*CC + t;
        float a = b1[h];
#pragma unroll 1
        for (int k4 = 0; k4 < CC/4; k4++) {
            float4 xv = sx24[k4]; int kk = 4*k4;
            a = fmaf(xv.x, w1[(kk+0)*HID+h], a);
            a = fmaf(xv.y, w1[(kk+1)*HID+h], a);
            a = fmaf(xv.z, w1[(kk+2)*HID+h], a);
            a = fmaf(xv.w, w1[(kk+3)*HID+h], a);
        }
        shid[h] = fmaxf(a, 0.f);
    }
    __syncthreads();

    float o = b2[t];
    const float4* sh4 = (const float4*)shid;
#pragma unroll 1
    for (int k4 = 0; k4 < HID/4; k4++) {
        float4 hv = sh4[k4]; int kk = 4*k4;
        o = fmaf(hv.x, w2[(kk+0)*CC+t], o);
        o = fmaf(hv.y, w2[(kk+1)*CC+t], o);
        o = fmaf(hv.z, w2[(kk+2)*CC+t], o);
        o = fmaf(hv.w, w2[(kk+3)*CC+t], o);
    }
    float pre2 = x2 + o;
    float mean2 = blockSum(pre2, sred, t) * (1.f/CC);
    float d2 = pre2 - mean2;
    float var2 = blockSum(d2*d2, sred, t) * (1.f/CC);
    xout[r*CC + t] = d2 * rsqrtf(var2 + EPSF) * ln5_s[t] + ln5_b[t];
}

// ---------------- K6a: hid = relu(y2 @ w1 + b1) ----------------------------
__global__ void __launch_bounds__(512, 1) k6a(
    const float* __restrict__ b1)
{
    extern __shared__ __align__(16) char dsm[];
    uint32_t* sA = (uint32_t*)dsm;
    uint32_t* sB = sA + 128 * PA;
    __shared__ float sbias[CC];

    int t = threadIdx.x, lane = t & 31, wid = t >> 5;
    int m0 = (wid & 3) * 32, n0 = (wid >> 2) * 64;
    int g = lane >> 2, tig = lane & 3;
    int tile = blockIdx.x;
    size_t base = (size_t)tile * 128;

    stageA(sA, g_y2, base, CC, 0, t);

#pragma unroll 1
    for (int nc = 0; nc < 4; nc++) {
        __syncthreads();
        if (t < CC) sbias[t] = b1[nc * CC + t];
        __syncthreads();

        float acc[2][8][4];
        initacc(acc, sbias, n0, tig);
#pragma unroll 1
        for (int kc = 0; kc < 4; kc++) {
            stageB(sB, g_w1T + (size_t)nc * CC * CC, CC, kc * 64, t);
            __syncthreads();
            gemm64(sA + kc * 64, sB, acc, m0, n0, g, tig);
            __syncthreads();
        }

#pragma unroll
        for (int mf = 0; mf < 2; mf++)
#pragma unroll
            for (int nf = 0; nf < 8; nf++) {
                int r = m0 + mf * 16 + g;
                int c = nc * CC + n0 + nf * 8 + 2 * tig;
#pragma unroll
                for (int h = 0; h < 2; h++) {
                    int rr = r + 8 * h;
                    float2 o;
                    o.x = fmaxf(acc[mf][nf][2*h],   0.f);
                    o.y = fmaxf(acc[mf][nf][2*h+1], 0.f);
                    *(float2*)(g_hid + (base + rr) * HID + c) = o;
                }
            }
    }
}

// ---------------- K6b: out = hid @ w2 + b2 + y2 ; LN6 ----------------------
__global__ void __launch_bounds__(512, 1) k6b(
    const float* __restrict__ b2,
    const float* __restrict__ ln6_s, const float* __restrict__ ln6_b,
    float* __restrict__ yout)
{
    extern __shared__ __align__(16) char dsm[];
    uint32_t* sA = (uint32_t*)dsm;
    uint32_t* sB = sA + 128 * PA;
    float* ln = (float*)dsm;
    __shared__ float sbias[CC];

    int t = threadIdx.x, lane = t & 31, wid = t >> 5;
    int m0 = (wid & 3) * 32, n0 = (wid >> 2) * 64;
    int g = lane >> 2, tig = lane & 3;
    int tile = blockIdx.x;
    size_t base = (size_t)tile * 128;

    if (t < CC) sbias[t] = b2[t];
    __syncthreads();

    float acc[2][8][4];
    initacc(acc, sbias, n0, tig);

#pragma unroll 1
    for (int kb = 0; kb < 4; kb++) {
        stageA(sA, g_hid, base, HID, kb * 256, t);
#pragma unroll 1
        for (int kc = 0; kc < 4; kc++) {
            stageB(sB, g_w2T, HID, kb * 256 + kc * 64, t);
            __syncthreads();
            gemm64(sA + kc * 64, sB, acc, m0, n0, g, tig);
            __syncthreads();
        }
    }

#pragma unroll
    for (int mf = 0; mf < 2; mf++)
#pragma unroll
        for (int nf = 0; nf < 8; nf++) {
            int r = m0 + mf * 16 + g;
            int c = n0 + nf * 8 + 2 * tig;
#pragma unroll
            for (int h = 0; h < 2; h++) {
                int rr = r + 8 * h;
                float2 yv = *(const float2*)(g_y2 + (base + rr) * CC + c);
                float2 o;
                o.x = acc[mf][nf][2*h]   + yv.x;
                o.y = acc[mf][nf][2*h+1] + yv.y;
                *(float2*)(ln + rr * PA + c) = o;
            }
        }
    __syncthreads();

    ln_rows128(ln, yout, base, ln6_s, ln6_b, t);
}

// ---------------- launch ---------------------------------------------------
extern "C" void kernel_launch(void* const* d_in, const int* in_sizes, int n_in,
                              void* d_out, int out_size)
{
    const float* x   = (const float*)d_in[0];
    const float* y   = (const float*)d_in[1];
    const float* Wq  = (const float*)d_in[2];
    const float* bq  = (const float*)d_in[3];
    const float* Wk  = (const float*)d_in[4];
    const float* bk  = (const float*)d_in[5];
    const float* Wv  = (const float*)d_in[6];
    const float* bv  = (const float*)d_in[7];
    const float* We  = (const float*)d_in[8];
    const float* be  = (const float*)d_in[9];
    const float* Woe = (const float*)d_in[10];
    const float* boe = (const float*)d_in[11];
    const float* Won = (const float*)d_in[12];
    const float* bon = (const float*)d_in[13];
    const float* m1w1 = (const float*)d_in[14];
    const float* m1b1 = (const float*)d_in[15];
    const float* m1w2 = (const float*)d_in[16];
    const float* m1b2 = (const float*)d_in[17];
    const float* m2w1 = (const float*)d_in[18];
    const float* m2b1 = (const float*)d_in[19];
    const float* m2w2 = (const float*)d_in[20];
    const float* m2b2 = (const float*)d_in[21];
    const float* ln1s = (const float*)d_in[22];
    const float* ln1b = (const float*)d_in[23];
    const float* ln3s = (const float*)d_in[24];
    const float* ln3b = (const float*)d_in[25];
    const float* ln4s = (const float*)d_in[26];
    const float* ln4b = (const float*)d_in[27];
    const float* ln5s = (const float*)d_in[28];
    const float* ln5b = (const float*)d_in[29];
    const float* ln6s = (const float*)d_in[30];
    const float* ln6b = (const float*)d_in[31];

    float* xout = (float*)d_out;                   // (8,128,256)
    float* yout = (float*)d_out + ROWS*CC;         // (8,128,128,256)

    cudaFuncSetAttribute(k2g, cudaFuncAttributeMaxDynamicSharedMemorySize, DSMEM);
    cudaFuncSetAttribute(k3g, cudaFuncAttributeMaxDynamicSharedMemorySize, DSMEM);
    cudaFuncSetAttribute(k6a, cudaFuncAttributeMaxDynamicSharedMemorySize, DSMEM);
    cudaFuncSetAttribute(k6b, cudaFuncAttributeMaxDynamicSharedMemorySize, DSMEM);

    ktrans<<<dim3(8, 8),  dim3(32, 8)>>>(We,   CC,  CC,  0);
    ktrans<<<dim3(8, 8),  dim3(32, 8)>>>(Woe,  CC,  CC,  1);
    ktrans<<<dim3(32, 8), dim3(32, 8)>>>(m2w1, CC,  HID, 2);
    ktrans<<<dim3(8, 32), dim3(32, 8)>>>(m2w2, HID, CC,  3);

    k1_node_qkv<<<ROWS, 256>>>(x, Wq, bq, Wk, bk, Wv, bv, ln1s, ln1b);
    k2g<<<ROWS, 512, DSMEM>>>(y, be);
    k3g<<<ROWS, 512, DSMEM>>>(y, boe, ln4s, ln4b);
    k4_softmax_agg<<<ROWS, 256>>>();
    k5_node_mlp<<<ROWS, 256>>>(Won, bon, m1w1, m1b1, m1w2, m1b2,
                               ln3s, ln3b, ln5s, ln5b, xout);
    k6a<<<ROWS, 512, DSMEM>>>(m2b1);
    k6b<<<ROWS, 512, DSMEM>>>(m2b2, ln6s, ln6b, yout);
}

// round 10
// speedup vs baseline: 2.9508x; 1.0632x over previous
#include <cuda_runtime.h>
#include <math.h>
#include <stdint.h>

#define BB   8
#define NN   128
#define CC   256
#define HID  1024
#define EPSF 1e-5f
#define ROWS (BB*NN)          /* 1024  */
#define EDGES (BB*NN*NN)      /* 131072 */
#define PA   260              /* A smem pitch in floats */
#define PB   68               /* B smem pitch in floats */

// ---------------- scratch (device globals; no allocation anywhere) ---------
__device__ float g_x1[ROWS*CC];
__device__ float g_q [ROWS*CC];
__device__ float g_k [ROWS*CC];
__device__ float g_v [ROWS*CC];
__device__ float g_agg[ROWS*CC];
__device__ float g_attn[(size_t)EDGES*CC];    // 134 MB
__device__ float g_y2 [(size_t)EDGES*CC];     // 134 MB
__device__ float g_hid[(size_t)EDGES*HID];    // 512 MB (L2-hot per CTA now)
__device__ float g_WeT [CC*CC];               // [n][k]
__device__ float g_WoeT[CC*CC];
__device__ float g_w1T [HID*CC];              // [h][k]
__device__ float g_w2T [CC*HID];              // [n][k]

// ---------------- mma.sync tf32 helpers ------------------------------------
__device__ __forceinline__ uint32_t f2tf(float f) {
    uint32_t r;
    asm("cvt.rna.tf32.f32 %0, %1;" : "=r"(r) : "f"(f));
    return r;
}
__device__ __forceinline__ void mma8(float* c, const uint32_t a[4],
                                     uint32_t b0, uint32_t b1) {
    asm volatile("mma.sync.aligned.m16n8k8.row.col.f32.tf32.tf32.f32 "
        "{%0,%1,%2,%3}, {%4,%5,%6,%7}, {%8,%9}, {%0,%1,%2,%3};"
        : "+f"(c[0]), "+f"(c[1]), "+f"(c[2]), "+f"(c[3])
        : "r"(a[0]), "r"(a[1]), "r"(a[2]), "r"(a[3]), "r"(b0), "r"(b1));
}

// stage A tile (128 x 256 floats) -> smem tf32, pitch PA. 512 threads.
__device__ __forceinline__ void stageA(uint32_t* __restrict__ sA,
                                       const float* __restrict__ src,
                                       size_t row0, int ld, int k0, int t) {
#pragma unroll
    for (int i = 0; i < 16; i++) {
        int f = t + 512 * i;
        int m = f >> 6, k = (f & 63) * 4;
        float4 v = *(const float4*)(src + (row0 + m) * (size_t)ld + k0 + k);
        uint4 u;
        u.x = f2tf(v.x); u.y = f2tf(v.y); u.z = f2tf(v.z); u.w = f2tf(v.w);
        *(uint4*)(sA + m * PA + k) = u;
    }
}
// stage B chunk (256 n x 64 k floats) -> smem tf32, pitch PB. 512 threads.
__device__ __forceinline__ void stageB(uint32_t* __restrict__ sB,
                                       const float* __restrict__ W,
                                       int ld, int k0, int t) {
#pragma unroll
    for (int i = 0; i < 8; i++) {
        int f = t + 512 * i;
        int n = f >> 4, k = (f & 15) * 4;
        float4 v = *(const float4*)(W + (size_t)n * ld + k0 + k);
        uint4 u;
        u.x = f2tf(v.x); u.y = f2tf(v.y); u.z = f2tf(v.z); u.w = f2tf(v.w);
        *(uint4*)(sB + n * PB + k) = u;
    }
}
// one K=64 chunk of MMAs. Pass sA pre-offset to the K-chunk's first column.
__device__ __forceinline__ void gemm64(const uint32_t* __restrict__ sA,
                                       const uint32_t* __restrict__ sB,
                                       float acc[2][8][4],
                                       int m0, int n0, int g, int tig) {
#pragma unroll
    for (int ks = 0; ks < 8; ks++) {
        int k0 = ks * 8;
        uint32_t af[2][4];
#pragma unroll
        for (int mf = 0; mf < 2; mf++) {
            int r = m0 + mf * 16 + g;
            af[mf][0] = sA[r * PA + k0 + tig];
            af[mf][1] = sA[(r + 8) * PA + k0 + tig];
            af[mf][2] = sA[r * PA + k0 + tig + 4];
            af[mf][3] = sA[(r + 8) * PA + k0 + tig + 4];
        }
#pragma unroll
        for (int nf = 0; nf < 8; nf++) {
            int n = n0 + nf * 8 + g;
            uint32_t b0 = sB[n * PB + k0 + tig];
            uint32_t b1 = sB[n * PB + k0 + tig + 4];
            mma8(acc[0][nf], af[0], b0, b1);
            mma8(acc[1][nf], af[1], b0, b1);
        }
    }
}
__device__ __forceinline__ void initacc(float acc[2][8][4],
                                        const float* sbias, int n0, int tig) {
#pragma unroll
    for (int mf = 0; mf < 2; mf++)
#pragma unroll
        for (int nf = 0; nf < 8; nf++) {
            int c = n0 + nf * 8 + 2 * tig;
            acc[mf][nf][0] = acc[mf][nf][2] = sbias[c];
            acc[mf][nf][1] = acc[mf][nf][3] = sbias[c + 1];
        }
}

// ---------------- misc fp32 helpers ----------------------------------------
__device__ __forceinline__ float warpSum(float v) {
#pragma unroll
    for (int o = 16; o > 0; o >>= 1) v += __shfl_xor_sync(0xffffffffu, v, o);
    return v;
}
__device__ __forceinline__ float blockSum(float v, float* sred, int t) {
    v = warpSum(v);
    __syncthreads();
    if ((t & 31) == 0) sred[t >> 5] = v;
    __syncthreads();
    float tot = 0.f;
#pragma unroll
    for (int w = 0; w < 8; w++) tot += sred[w];
    return tot;
}
// LN over 128 rows x 256 cols in ln[r*PA + c] (512 threads)
__device__ __forceinline__ void ln_rows128(const float* ln, float* __restrict__ out,
                                           size_t base, const float* __restrict__ s,
                                           const float* __restrict__ bsh, int t) {
    int w = t >> 5, l = t & 31;
#pragma unroll 1
    for (int u = 0; u < 8; u++) {
        int r = u * 16 + w;
        float sm = 0.f, sq = 0.f;
#pragma unroll
        for (int c0 = 0; c0 < CC; c0 += 32) {
            float v = ln[r * PA + c0 + l];
            sm += v; sq = fmaf(v, v, sq);
        }
        sm = warpSum(sm); sq = warpSum(sq);
        float mean = sm * (1.f / CC);
        float rstd = rsqrtf(sq * (1.f / CC) - mean * mean + EPSF);
#pragma unroll
        for (int c0 = 0; c0 < CC; c0 += 32) {
            int c = c0 + l;
            out[(base + r) * CC + c] = (ln[r * PA + c] - mean) * rstd * s[c] + bsh[c];
        }
    }
}

// ---------------- weight transpose -----------------------------------------
__global__ void ktrans(const float* __restrict__ src, int R, int Cc, int which) {
    float* dst = which == 0 ? g_WeT : which == 1 ? g_WoeT
               : which == 2 ? g_w1T : g_w2T;
    __shared__ float tb[32][33];
    int bx = blockIdx.x * 32, by = blockIdx.y * 32;
    int tx = threadIdx.x, ty = threadIdx.y;
#pragma unroll
    for (int i = 0; i < 32; i += 8)
        tb[ty + i][tx] = src[(size_t)(by + ty + i) * Cc + bx + tx];
    __syncthreads();
#pragma unroll
    for (int i = 0; i < 32; i += 8)
        dst[(size_t)(bx + ty + i) * R + by + tx] = tb[tx][ty + i];
}

// ---------------- K1: LN1 + qkv --------------------------------------------
__global__ void __launch_bounds__(256) k1_node_qkv(
    const float* __restrict__ x,
    const float* __restrict__ Wq, const float* __restrict__ bq,
    const float* __restrict__ Wk, const float* __restrict__ bk,
    const float* __restrict__ Wv, const float* __restrict__ bv,
    const float* __restrict__ ln1_s, const float* __restrict__ ln1_b)
{
    __shared__ __align__(16) float sx[CC];
    __shared__ float sred[8];
    int r = blockIdx.x, t = threadIdx.x;

    float xv = x[r*CC + t];
    float mean = blockSum(xv, sred, t) * (1.f/CC);
    float d = xv - mean;
    float var = blockSum(d*d, sred, t) * (1.f/CC);
    float x1 = d * rsqrtf(var + EPSF) * ln1_s[t] + ln1_b[t];
    sx[t] = x1;
    g_x1[r*CC + t] = x1;
    __syncthreads();

    float aq = bq[t], ak = bk[t], av = bv[t];
    const float4* sx4 = (const float4*)sx;
#pragma unroll 1
    for (int k4 = 0; k4 < CC/4; k4++) {
        float4 v = sx4[k4]; int kk = 4*k4;
        aq = fmaf(v.x, Wq[(kk+0)*CC+t], aq);
        aq = fmaf(v.y, Wq[(kk+1)*CC+t], aq);
        aq = fmaf(v.z, Wq[(kk+2)*CC+t], aq);
        aq = fmaf(v.w, Wq[(kk+3)*CC+t], aq);
        ak = fmaf(v.x, Wk[(kk+0)*CC+t], ak);
        ak = fmaf(v.y, Wk[(kk+1)*CC+t], ak);
        ak = fmaf(v.z, Wk[(kk+2)*CC+t], ak);
        ak = fmaf(v.w, Wk[(kk+3)*CC+t], ak);
        av = fmaf(v.x, Wv[(kk+0)*CC+t], av);
        av = fmaf(v.y, Wv[(kk+1)*CC+t], av);
        av = fmaf(v.z, Wv[(kk+2)*CC+t], av);
        av = fmaf(v.w, Wv[(kk+3)*CC+t], av);
    }
    g_q[r*CC+t] = aq;  g_k[r*CC+t] = ak;  g_v[r*CC+t] = av;
}

#define DSMEM ((128*PA + 256*PB) * 4)   /* 202,752 B */

// ---------------- K23: fused e-proj + attn + edge_out + LN4 ----------------
__global__ void __launch_bounds__(512, 1) k23(
    const float* __restrict__ y, const float* __restrict__ be,
    const float* __restrict__ boe,
    const float* __restrict__ ln4_s, const float* __restrict__ ln4_b)
{
    extern __shared__ __align__(16) char dsm[];
    uint32_t* sA = (uint32_t*)dsm;
    uint32_t* sB = sA + 128 * PA;
    float* ln = (float*)dsm;
    __shared__ float s_q[CC], s_bb[CC], s_b2[CC];

    int t = threadIdx.x, lane = t & 31, wid = t >> 5;
    int m0 = (wid & 3) * 32, n0 = (wid >> 2) * 64;
    int g = lane >> 2, tig = lane & 3;
    int tile = blockIdx.x;
    size_t base = (size_t)tile * 128;
    int krow = (tile >> 7) << 7;

    if (t < CC) {
        s_bb[t] = be[t];
        s_b2[t] = boe[t];
        s_q[t]  = g_q[(size_t)tile*CC + t] * 0.17677669529663687f;  // 1/sqrt(32)
    }
    stageA(sA, y, base, CC, 0, t);
    __syncthreads();

    // ---- GEMM1: e = y @ We + be -------------------------------------------
    float acc[2][8][4];
    initacc(acc, s_bb, n0, tig);
#pragma unroll 1
    for (int kc = 0; kc < 4; kc++) {
        stageB(sB, g_WeT, CC, kc * 64, t);
        __syncthreads();
        gemm64(sA + kc * 64, sB, acc, m0, n0, g, tig);
        __syncthreads();
    }

    // ---- epilogue1: attn = q*k/sqrt(dk)*(e+1)*e ---------------------------
    // write fp32 to g_attn (for k4) AND tf32 into sA (A operand of GEMM2).
#pragma unroll
    for (int mf = 0; mf < 2; mf++)
#pragma unroll
        for (int nf = 0; nf < 8; nf++) {
            int r = m0 + mf * 16 + g;
            int c = n0 + nf * 8 + 2 * tig;
#pragma unroll
            for (int h = 0; h < 2; h++) {
                int rr = r + 8 * h;
                float e0 = acc[mf][nf][2*h], e1 = acc[mf][nf][2*h+1];
                float2 kv = *(const float2*)(g_k + (size_t)(krow + rr) * CC + c);
                float2 o;
                o.x = s_q[c]   * kv.x * (e0 + 1.f) * e0;
                o.y = s_q[c+1] * kv.y * (e1 + 1.f) * e1;
                *(float2*)(g_attn + (base + rr) * CC + c) = o;
                sA[rr * PA + c]     = f2tf(o.x);
                sA[rr * PA + c + 1] = f2tf(o.y);
            }
        }
    __syncthreads();

    // ---- GEMM2: edge_out = attn @ Woe + boe -------------------------------
    initacc(acc, s_b2, n0, tig);
#pragma unroll 1
    for (int kc = 0; kc < 4; kc++) {
        stageB(sB, g_WoeT, CC, kc * 64, t);
        __syncthreads();
        gemm64(sA + kc * 64, sB, acc, m0, n0, g, tig);
        __syncthreads();
    }

    // ---- epilogue2: + y residual -> ln buffer -> LN4 -> g_y2 --------------
#pragma unroll
    for (int mf = 0; mf < 2; mf++)
#pragma unroll
        for (int nf = 0; nf < 8; nf++) {
            int r = m0 + mf * 16 + g;
            int c = n0 + nf * 8 + 2 * tig;
#pragma unroll
            for (int h = 0; h < 2; h++) {
                int rr = r + 8 * h;
                float2 yv = *(const float2*)(y + (base + rr) * CC + c);
                float2 o;
                o.x = acc[mf][nf][2*h]   + yv.x;
                o.y = acc[mf][nf][2*h+1] + yv.y;
                *(float2*)(ln + rr * PA + c) = o;
            }
        }
    __syncthreads();

    ln_rows128(ln, g_y2, base, ln4_s, ln4_b, t);
}

// ---------------- K4: softmax over j + V aggregation -----------------------
__global__ void __launch_bounds__(256) k4_softmax_agg()
{
    int ri = blockIdx.x;
    int b  = ri >> 7;
    int c  = threadIdx.x;
    const float* ap = g_attn + (size_t)ri * NN * CC + c;
    const float* vp = g_v    + (size_t)(b << 7) * CC + c;

    float m = -3.4e38f, s = 0.f, acc = 0.f;
#pragma unroll 4
    for (int j = 0; j < NN; j++) {
        float a    = ap[(size_t)j * CC];
        float nm   = fmaxf(m, a);
        float corr = __expf(m - nm);
        float p    = __expf(a - nm);
        s   = s   * corr + p;
        acc = acc * corr + p * vp[(size_t)j * CC];
        m = nm;
    }
    g_agg[ri*CC + c] = acc / s;
}

// ---------------- K5: node out proj + LN3 + MLP + LN5 ----------------------
__global__ void __launch_bounds__(256) k5_node_mlp(
    const float* __restrict__ Won, const float* __restrict__ bon,
    const float* __restrict__ w1, const float* __restrict__ b1,
    const float* __restrict__ w2, const float* __restrict__ b2,
    const float* __restrict__ ln3_s, const float* __restrict__ ln3_b,
    const float* __restrict__ ln5_s, const float* __restrict__ ln5_b,
    float* __restrict__ xout)
{
    __shared__ __align__(16) float sagg[CC];
    __shared__ __align__(16) float sx2[CC];
    __shared__ __align__(16) float shid[HID];
    __shared__ float sred[8];
    int r = blockIdx.x, t = threadIdx.x;

    sagg[t] = g_agg[r*CC + t];
    __syncthreads();

    float no = bon[t];
    const float4* sa4 = (const float4*)sagg;
#pragma unroll 1
    for (int k4 = 0; k4 < CC/4; k4++) {
        float4 av = sa4[k4]; int kk = 4*k4;
        no = fmaf(av.x, Won[(kk+0)*CC+t], no);
        no = fmaf(av.y, Won[(kk+1)*CC+t], no);
        no = fmaf(av.z, Won[(kk+2)*CC+t], no);
        no = fmaf(av.w, Won[(kk+3)*CC+t], no);
    }
    float pre = g_x1[r*CC + t] + no;

    float mean = blockSum(pre, sred, t) * (1.f/CC);
    float d = pre - mean;
    float var = blockSum(d*d, sred, t) * (1.f/CC);
    float x2 = d * rsqrtf(var + EPSF) * ln3_s[t] + ln3_b[t];
    sx2[t] = x2;
    __syncthreads();

    const float4* sx24 = (const float4*)sx2;
#pragma unroll 1
    for (int hb = 0; hb < 4; hb++) {
        int h = hb*CC + t;
        float a = b1[h];
#pragma unroll 1
        for (int k4 = 0; k4 < CC/4; k4++) {
            float4 xv = sx24[k4]; int kk = 4*k4;
            a = fmaf(xv.x, w1[(kk+0)*HID+h], a);
            a = fmaf(xv.y, w1[(kk+1)*HID+h], a);
            a = fmaf(xv.z, w1[(kk+2)*HID+h], a);
            a = fmaf(xv.w, w1[(kk+3)*HID+h], a);
        }
        shid[h] = fmaxf(a, 0.f);
    }
    __syncthreads();

    float o = b2[t];
    const float4* sh4 = (const float4*)shid;
#pragma unroll 1
    for (int k4 = 0; k4 < HID/4; k4++) {
        float4 hv = sh4[k4]; int kk = 4*k4;
        o = fmaf(hv.x, w2[(kk+0)*CC+t], o);
        o = fmaf(hv.y, w2[(kk+1)*CC+t], o);
        o = fmaf(hv.z, w2[(kk+2)*CC+t], o);
        o = fmaf(hv.w, w2[(kk+3)*CC+t], o);
    }
    float pre2 = x2 + o;
    float mean2 = blockSum(pre2, sred, t) * (1.f/CC);
    float d2 = pre2 - mean2;
    float var2 = blockSum(d2*d2, sred, t) * (1.f/CC);
    xout[r*CC + t] = d2 * rsqrtf(var2 + EPSF) * ln5_s[t] + ln5_b[t];
}

// ---------------- K6f: fused edge MLP (hid stays L2-hot) + LN6 -------------
__global__ void __launch_bounds__(512, 1) k6f(
    const float* __restrict__ b1, const float* __restrict__ b2,
    const float* __restrict__ ln6_s, const float* __restrict__ ln6_b,
    float* __restrict__ yout)
{
    extern __shared__ __align__(16) char dsm[];
    uint32_t* sA = (uint32_t*)dsm;
    uint32_t* sB = sA + 128 * PA;
    float* ln = (float*)dsm;
    __shared__ float sbias[CC];

    int t = threadIdx.x, lane = t & 31, wid = t >> 5;
    int m0 = (wid & 3) * 32, n0 = (wid >> 2) * 64;
    int g = lane >> 2, tig = lane & 3;
    int tile = blockIdx.x;
    size_t base = (size_t)tile * 128;

    // ======== phase 1: hid = relu(y2 @ w1 + b1) ============================
    stageA(sA, g_y2, base, CC, 0, t);

#pragma unroll 1
    for (int nc = 0; nc < 4; nc++) {
        __syncthreads();
        if (t < CC) sbias[t] = b1[nc * CC + t];
        __syncthreads();

        float acc[2][8][4];
        initacc(acc, sbias, n0, tig);
#pragma unroll 1
        for (int kc = 0; kc < 4; kc++) {
            stageB(sB, g_w1T + (size_t)nc * CC * CC, CC, kc * 64, t);
            __syncthreads();
            gemm64(sA + kc * 64, sB, acc, m0, n0, g, tig);
            __syncthreads();
        }

#pragma unroll
        for (int mf = 0; mf < 2; mf++)
#pragma unroll
            for (int nf = 0; nf < 8; nf++) {
                int r = m0 + mf * 16 + g;
                int c = nc * CC + n0 + nf * 8 + 2 * tig;
#pragma unroll
                for (int h = 0; h < 2; h++) {
                    int rr = r + 8 * h;
                    float2 o;
                    o.x = fmaxf(acc[mf][nf][2*h],   0.f);
                    o.y = fmaxf(acc[mf][nf][2*h+1], 0.f);
                    *(float2*)(g_hid + (base + rr) * HID + c) = o;
                }
            }
    }
    __syncthreads();   // phase boundary: hid visible block-wide (L2-hot)

    // ======== phase 2: out = hid @ w2 + b2 + y2 ; LN6 ======================
    if (t < CC) sbias[t] = b2[t];
    __syncthreads();

    float acc[2][8][4];
    initacc(acc, sbias, n0, tig);

#pragma unroll 1
    for (int kb = 0; kb < 4; kb++) {
        stageA(sA, g_hid, base, HID, kb * 256, t);
#pragma unroll 1
        for (int kc = 0; kc < 4; kc++) {
            stageB(sB, g_w2T, HID, kb * 256 + kc * 64, t);
            __syncthreads();
            gemm64(sA + kc * 64, sB, acc, m0, n0, g, tig);
            __syncthreads();
        }
    }

#pragma unroll
    for (int mf = 0; mf < 2; mf++)
#pragma unroll
        for (int nf = 0; nf < 8; nf++) {
            int r = m0 + mf * 16 + g;
            int c = n0 + nf * 8 + 2 * tig;
#pragma unroll
            for (int h = 0; h < 2; h++) {
                int rr = r + 8 * h;
                float2 yv = *(const float2*)(g_y2 + (base + rr) * CC + c);
                float2 o;
                o.x = acc[mf][nf][2*h]   + yv.x;
                o.y = acc[mf][nf][2*h+1] + yv.y;
                *(float2*)(ln + rr * PA + c) = o;
            }
        }
    __syncthreads();

    ln_rows128(ln, yout, base, ln6_s, ln6_b, t);
}

// ---------------- launch ---------------------------------------------------
extern "C" void kernel_launch(void* const* d_in, const int* in_sizes, int n_in,
                              void* d_out, int out_size)
{
    const float* x   = (const float*)d_in[0];
    const float* y   = (const float*)d_in[1];
    const float* Wq  = (const float*)d_in[2];
    const float* bq  = (const float*)d_in[3];
    const float* Wk  = (const float*)d_in[4];
    const float* bk  = (const float*)d_in[5];
    const float* Wv  = (const float*)d_in[6];
    const float* bv  = (const float*)d_in[7];
    const float* We  = (const float*)d_in[8];
    const float* be  = (const float*)d_in[9];
    const float* Woe = (const float*)d_in[10];
    const float* boe = (const float*)d_in[11];
    const float* Won = (const float*)d_in[12];
    const float* bon = (const float*)d_in[13];
    const float* m1w1 = (const float*)d_in[14];
    const float* m1b1 = (const float*)d_in[15];
    const float* m1w2 = (const float*)d_in[16];
    const float* m1b2 = (const float*)d_in[17];
    const float* m2w1 = (const float*)d_in[18];
    const float* m2b1 = (const float*)d_in[19];
    const float* m2w2 = (const float*)d_in[20];
    const float* m2b2 = (const float*)d_in[21];
    const float* ln1s = (const float*)d_in[22];
    const float* ln1b = (const float*)d_in[23];
    const float* ln3s = (const float*)d_in[24];
    const float* ln3b = (const float*)d_in[25];
    const float* ln4s = (const float*)d_in[26];
    const float* ln4b = (const float*)d_in[27];
    const float* ln5s = (const float*)d_in[28];
    const float* ln5b = (const float*)d_in[29];
    const float* ln6s = (const float*)d_in[30];
    const float* ln6b = (const float*)d_in[31];

    float* xout = (float*)d_out;                   // (8,128,256)
    float* yout = (float*)d_out + ROWS*CC;         // (8,128,128,256)

    cudaFuncSetAttribute(k23, cudaFuncAttributeMaxDynamicSharedMemorySize, DSMEM);
    cudaFuncSetAttribute(k6f, cudaFuncAttributeMaxDynamicSharedMemorySize, DSMEM);

    ktrans<<<dim3(8, 8),  dim3(32, 8)>>>(We,   CC,  CC,  0);
    ktrans<<<dim3(8, 8),  dim3(32, 8)>>>(Woe,  CC,  CC,  1);
    ktrans<<<dim3(32, 8), dim3(32, 8)>>>(m2w1, CC,  HID, 2);
    ktrans<<<dim3(8, 32), dim3(32, 8)>>>(m2w2, HID, CC,  3);

    k1_node_qkv<<<ROWS, 256>>>(x, Wq, bq, Wk, bk, Wv, bv, ln1s, ln1b);
    k23<<<ROWS, 512, DSMEM>>>(y, be, boe, ln4s, ln4b);
    k4_softmax_agg<<<ROWS, 256>>>();
    k5_node_mlp<<<ROWS, 256>>>(Won, bon, m1w1, m1b1, m1w2, m1b2,
                               ln3s, ln3b, ln5s, ln5b, xout);
    k6f<<<ROWS, 512, DSMEM>>>(m2b1, m2b2, ln6s, ln6b, yout);
}

// round 11
// speedup vs baseline: 3.0656x; 1.0389x over previous
#include <cuda_runtime.h>
#include <math.h>
#include <stdint.h>

#define BB   8
#define NN   128
#define CC   256
#define HID  1024
#define EPSF 1e-5f
#define ROWS (BB*NN)          /* 1024  */
#define EDGES (BB*NN*NN)      /* 131072 */
#define PA   260              /* A smem pitch in floats */
#define PB   68               /* B smem pitch in floats */

// ---------------- scratch (device globals; no allocation anywhere) ---------
__device__ float g_x1[ROWS*CC];
__device__ float g_q [ROWS*CC];
__device__ float g_k [ROWS*CC];
__device__ float g_v [ROWS*CC];
__device__ float g_agg[ROWS*CC];
__device__ float g_y2 [(size_t)EDGES*CC];     // 134 MB
__device__ float g_hid[(size_t)EDGES*HID];    // 512 MB (CTA-local, L2-hot)
__device__ float g_WeT [CC*CC];               // [n][k]
__device__ float g_WoeT[CC*CC];
__device__ float g_w1T [HID*CC];              // [h][k]
__device__ float g_w2T [CC*HID];              // [n][k]

// ---------------- mma.sync tf32 helpers ------------------------------------
__device__ __forceinline__ uint32_t f2tf(float f) {
    uint32_t r;
    asm("cvt.rna.tf32.f32 %0, %1;" : "=r"(r) : "f"(f));
    return r;
}
__device__ __forceinline__ void mma8(float* c, const uint32_t a[4],
                                     uint32_t b0, uint32_t b1) {
    asm volatile("mma.sync.aligned.m16n8k8.row.col.f32.tf32.tf32.f32 "
        "{%0,%1,%2,%3}, {%4,%5,%6,%7}, {%8,%9}, {%0,%1,%2,%3};"
        : "+f"(c[0]), "+f"(c[1]), "+f"(c[2]), "+f"(c[3])
        : "r"(a[0]), "r"(a[1]), "r"(a[2]), "r"(a[3]), "r"(b0), "r"(b1));
}

// stage A tile (128 x 256 floats) -> smem tf32, pitch PA. 512 threads.
__device__ __forceinline__ void stageA(uint32_t* __restrict__ sA,
                                       const float* __restrict__ src,
                                       size_t row0, int ld, int k0, int t) {
#pragma unroll
    for (int i = 0; i < 16; i++) {
        int f = t + 512 * i;
        int m = f >> 6, k = (f & 63) * 4;
        float4 v = *(const float4*)(src + (row0 + m) * (size_t)ld + k0 + k);
        uint4 u;
        u.x = f2tf(v.x); u.y = f2tf(v.y); u.z = f2tf(v.z); u.w = f2tf(v.w);
        *(uint4*)(sA + m * PA + k) = u;
    }
}
// prefetch B chunk (256 n x 64 k floats) into registers. 512 threads.
__device__ __forceinline__ void ldgB4(float4* __restrict__ pB,
                                      const float* __restrict__ W,
                                      int ld, int k0, int t) {
#pragma unroll
    for (int i = 0; i < 8; i++) {
        int f = t + 512 * i;
        int n = f >> 4, k = (f & 15) * 4;
        pB[i] = *(const float4*)(W + (size_t)n * ld + k0 + k);
    }
}
// store prefetched B regs -> smem tf32, pitch PB.
__device__ __forceinline__ void stsB4(uint32_t* __restrict__ sB,
                                      const float4* __restrict__ pB, int t) {
#pragma unroll
    for (int i = 0; i < 8; i++) {
        int f = t + 512 * i;
        int n = f >> 4, k = (f & 15) * 4;
        uint4 u;
        u.x = f2tf(pB[i].x); u.y = f2tf(pB[i].y);
        u.z = f2tf(pB[i].z); u.w = f2tf(pB[i].w);
        *(uint4*)(sB + n * PB + k) = u;
    }
}
// one K=64 chunk of MMAs. Pass sA pre-offset to the K-chunk's first column.
__device__ __forceinline__ void gemm64(const uint32_t* __restrict__ sA,
                                       const uint32_t* __restrict__ sB,
                                       float acc[2][8][4],
                                       int m0, int n0, int g, int tig) {
#pragma unroll
    for (int ks = 0; ks < 8; ks++) {
        int k0 = ks * 8;
        uint32_t af[2][4];
#pragma unroll
        for (int mf = 0; mf < 2; mf++) {
            int r = m0 + mf * 16 + g;
            af[mf][0] = sA[r * PA + k0 + tig];
            af[mf][1] = sA[(r + 8) * PA + k0 + tig];
            af[mf][2] = sA[r * PA + k0 + tig + 4];
            af[mf][3] = sA[(r + 8) * PA + k0 + tig + 4];
        }
#pragma unroll
        for (int nf = 0; nf < 8; nf++) {
            int n = n0 + nf * 8 + g;
            uint32_t b0 = sB[n * PB + k0 + tig];
            uint32_t b1 = sB[n * PB + k0 + tig + 4];
            mma8(acc[0][nf], af[0], b0, b1);
            mma8(acc[1][nf], af[1], b0, b1);
        }
    }
}
__device__ __forceinline__ void initacc(float acc[2][8][4],
                                        const float* sbias, int n0, int tig) {
#pragma unroll
    for (int mf = 0; mf < 2; mf++)
#pragma unroll
        for (int nf = 0; nf < 8; nf++) {
            int c = n0 + nf * 8 + 2 * tig;
            acc[mf][nf][0] = acc[mf][nf][2] = sbias[c];
            acc[mf][nf][1] = acc[mf][nf][3] = sbias[c + 1];
        }
}

// ---------------- misc fp32 helpers ----------------------------------------
__device__ __forceinline__ float warpSum(float v) {
#pragma unroll
    for (int o = 16; o > 0; o >>= 1) v += __shfl_xor_sync(0xffffffffu, v, o);
    return v;
}
__device__ __forceinline__ float blockSum(float v, float* sred, int t) {
    v = warpSum(v);
    __syncthreads();
    if ((t & 31) == 0) sred[t >> 5] = v;
    __syncthreads();
    float tot = 0.f;
#pragma unroll
    for (int w = 0; w < 8; w++) tot += sred[w];
    return tot;
}
// LN over 128 rows x 256 cols in ln[r*PA + c] (512 threads)
__device__ __forceinline__ void ln_rows128(const float* ln, float* __restrict__ out,
                                           size_t base, const float* __restrict__ s,
                                           const float* __restrict__ bsh, int t) {
    int w = t >> 5, l = t & 31;
#pragma unroll 1
    for (int u = 0; u < 8; u++) {
        int r = u * 16 + w;
        float sm = 0.f, sq = 0.f;
#pragma unroll
        for (int c0 = 0; c0 < CC; c0 += 32) {
            float v = ln[r * PA + c0 + l];
            sm += v; sq = fmaf(v, v, sq);
        }
        sm = warpSum(sm); sq = warpSum(sq);
        float mean = sm * (1.f / CC);
        float rstd = rsqrtf(sq * (1.f / CC) - mean * mean + EPSF);
#pragma unroll
        for (int c0 = 0; c0 < CC; c0 += 32) {
            int c = c0 + l;
            out[(base + r) * CC + c] = (ln[r * PA + c] - mean) * rstd * s[c] + bsh[c];
        }
    }
}

// ---------------- weight transpose -----------------------------------------
__global__ void ktrans(const float* __restrict__ src, int R, int Cc, int which) {
    float* dst = which == 0 ? g_WeT : which == 1 ? g_WoeT
               : which == 2 ? g_w1T : g_w2T;
    __shared__ float tb[32][33];
    int bx = blockIdx.x * 32, by = blockIdx.y * 32;
    int tx = threadIdx.x, ty = threadIdx.y;
#pragma unroll
    for (int i = 0; i < 32; i += 8)
        tb[ty + i][tx] = src[(size_t)(by + ty + i) * Cc + bx + tx];
    __syncthreads();
#pragma unroll
    for (int i = 0; i < 32; i += 8)
        dst[(size_t)(bx + ty + i) * R + by + tx] = tb[tx][ty + i];
}

// ---------------- K1: LN1 + qkv --------------------------------------------
__global__ void __launch_bounds__(256) k1_node_qkv(
    const float* __restrict__ x,
    const float* __restrict__ Wq, const float* __restrict__ bq,
    const float* __restrict__ Wk, const float* __restrict__ bk,
    const float* __restrict__ Wv, const float* __restrict__ bv,
    const float* __restrict__ ln1_s, const float* __restrict__ ln1_b)
{
    __shared__ __align__(16) float sx[CC];
    __shared__ float sred[8];
    int r = blockIdx.x, t = threadIdx.x;

    float xv = x[r*CC + t];
    float mean = blockSum(xv, sred, t) * (1.f/CC);
    float d = xv - mean;
    float var = blockSum(d*d, sred, t) * (1.f/CC);
    float x1 = d * rsqrtf(var + EPSF) * ln1_s[t] + ln1_b[t];
    sx[t] = x1;
    g_x1[r*CC + t] = x1;
    __syncthreads();

    float aq = bq[t], ak = bk[t], av = bv[t];
    const float4* sx4 = (const float4*)sx;
#pragma unroll 1
    for (int k4 = 0; k4 < CC/4; k4++) {
        float4 v = sx4[k4]; int kk = 4*k4;
        aq = fmaf(v.x, Wq[(kk+0)*CC+t], aq);
        aq = fmaf(v.y, Wq[(kk+1)*CC+t], aq);
        aq = fmaf(v.z, Wq[(kk+2)*CC+t], aq);
        aq = fmaf(v.w, Wq[(kk+3)*CC+t], aq);
        ak = fmaf(v.x, Wk[(kk+0)*CC+t], ak);
        ak = fmaf(v.y, Wk[(kk+1)*CC+t], ak);
        ak = fmaf(v.z, Wk[(kk+2)*CC+t], ak);
        ak = fmaf(v.w, Wk[(kk+3)*CC+t], ak);
        av = fmaf(v.x, Wv[(kk+0)*CC+t], av);
        av = fmaf(v.y, Wv[(kk+1)*CC+t], av);
        av = fmaf(v.z, Wv[(kk+2)*CC+t], av);
        av = fmaf(v.w, Wv[(kk+3)*CC+t], av);
    }
    g_q[r*CC+t] = aq;  g_k[r*CC+t] = ak;  g_v[r*CC+t] = av;
}

#define DSMEM ((128*PA + 256*PB) * 4)   /* 202,752 B */

// ---------------- K23: e-proj + attn + softmax-agg + edge_out + LN4 --------
__global__ void __launch_bounds__(512, 1) k23(
    const float* __restrict__ y, const float* __restrict__ be,
    const float* __restrict__ boe,
    const float* __restrict__ ln4_s, const float* __restrict__ ln4_b)
{
    extern __shared__ __align__(16) char dsm[];
    uint32_t* sA = (uint32_t*)dsm;
    uint32_t* sB = sA + 128 * PA;
    float* ln = (float*)dsm;
    __shared__ float s_q[CC], s_bb[CC], s_b2[CC];

    int t = threadIdx.x, lane = t & 31, wid = t >> 5;
    int m0 = (wid & 3) * 32, n0 = (wid >> 2) * 64;
    int g = lane >> 2, tig = lane & 3;
    int tile = blockIdx.x;
    size_t base = (size_t)tile * 128;
    int krow = (tile >> 7) << 7;

    if (t < CC) {
        s_bb[t] = be[t];
        s_b2[t] = boe[t];
        s_q[t]  = g_q[(size_t)tile*CC + t] * 0.17677669529663687f;  // 1/sqrt(32)
    }
    stageA(sA, y, base, CC, 0, t);
    float4 pB[8];
    ldgB4(pB, g_WeT, CC, 0, t);
    __syncthreads();                 // sA + s_* ready

    // ---- GEMM1: e = y @ We + be (B double-buffered through regs) ----------
    float acc[2][8][4];
    initacc(acc, s_bb, n0, tig);
#pragma unroll 1
    for (int kc = 0; kc < 4; kc++) {
        stsB4(sB, pB, t);
        if (kc < 3) ldgB4(pB, g_WeT, CC, (kc + 1) * 64, t);
        __syncthreads();             // sB staged
        gemm64(sA + kc * 64, sB, acc, m0, n0, g, tig);
        __syncthreads();             // all warps done reading sB
    }

    // prefetch GEMM2's first B chunk; hides behind epilogue + softmax
    ldgB4(pB, g_WoeT, CC, 0, t);

    // ---- epilogue1: attn = q*k/sqrt(dk)*(e+1)*e -> tf32 into sA -----------
#pragma unroll
    for (int mf = 0; mf < 2; mf++)
#pragma unroll
        for (int nf = 0; nf < 8; nf++) {
            int r = m0 + mf * 16 + g;
            int c = n0 + nf * 8 + 2 * tig;
#pragma unroll
            for (int h = 0; h < 2; h++) {
                int rr = r + 8 * h;
                float e0 = acc[mf][nf][2*h], e1 = acc[mf][nf][2*h+1];
                float2 kv = *(const float2*)(g_k + (size_t)(krow + rr) * CC + c);
                sA[rr * PA + c]     = f2tf(s_q[c]   * kv.x * (e0 + 1.f) * e0);
                sA[rr * PA + c + 1] = f2tf(s_q[c+1] * kv.y * (e1 + 1.f) * e1);
            }
        }
    __syncthreads();                 // attn tile visible

    // ---- fused softmax over j + V aggregation (tile-local!) ---------------
    {
        float* red = (float*)sB;     // 1536 floats of partials
        int c = t & 255, half = t >> 8;
        const float* vp = g_v + (size_t)(krow + half * 64) * CC + c;
        float m = -3.4e38f, s = 0.f, a = 0.f;
#pragma unroll 4
        for (int j = 0; j < 64; j++) {
            float av = __uint_as_float(sA[(half * 64 + j) * PA + c]);
            float nm = fmaxf(m, av);
            float corr = __expf(m - nm);
            float p = __expf(av - nm);
            s = s * corr + p;
            a = a * corr + p * vp[(size_t)j * CC];
            m = nm;
        }
        red[half * 256 + c]        = m;
        red[512 + half * 256 + c]  = s;
        red[1024 + half * 256 + c] = a;
        __syncthreads();
        if (t < 256) {
            float m0_ = red[c],       m1_ = red[256 + c];
            float s0  = red[512 + c], s1  = red[768 + c];
            float a0  = red[1024 + c], a1 = red[1280 + c];
            float mm = fmaxf(m0_, m1_);
            float e0 = __expf(m0_ - mm), e1 = __expf(m1_ - mm);
            g_agg[(size_t)tile * CC + c] = (a0 * e0 + a1 * e1) / (s0 * e0 + s1 * e1);
        }
    }
    __syncthreads();                 // red reads done; sB free

    // ---- GEMM2: edge_out = attn @ Woe + boe -------------------------------
    initacc(acc, s_b2, n0, tig);
#pragma unroll 1
    for (int kc = 0; kc < 4; kc++) {
        stsB4(sB, pB, t);
        if (kc < 3) ldgB4(pB, g_WoeT, CC, (kc + 1) * 64, t);
        __syncthreads();
        gemm64(sA + kc * 64, sB, acc, m0, n0, g, tig);
        __syncthreads();
    }

    // ---- epilogue2: + y residual -> ln buffer -> LN4 -> g_y2 --------------
#pragma unroll
    for (int mf = 0; mf < 2; mf++)
#pragma unroll
        for (int nf = 0; nf < 8; nf++) {
            int r = m0 + mf * 16 + g;
            int c = n0 + nf * 8 + 2 * tig;
#pragma unroll
            for (int h = 0; h < 2; h++) {
                int rr = r + 8 * h;
                float2 yv = *(const float2*)(y + (base + rr) * CC + c);
                float2 o;
                o.x = acc[mf][nf][2*h]   + yv.x;
                o.y = acc[mf][nf][2*h+1] + yv.y;
                *(float2*)(ln + rr * PA + c) = o;
            }
        }
    __syncthreads();

    ln_rows128(ln, g_y2, base, ln4_s, ln4_b, t);
}

// ---------------- K5: node out proj + LN3 + MLP + LN5 ----------------------
__global__ void __launch_bounds__(256) k5_node_mlp(
    const float* __restrict__ Won, const float* __restrict__ bon,
    const float* __restrict__ w1, const float* __restrict__ b1,
    const float* __restrict__ w2, const float* __restrict__ b2,
    const float* __restrict__ ln3_s, const float* __restrict__ ln3_b,
    const float* __restrict__ ln5_s, const float* __restrict__ ln5_b,
    float* __restrict__ xout)
{
    __shared__ __align__(16) float sagg[CC];
    __shared__ __align__(16) float sx2[CC];
    __shared__ __align__(16) float shid[HID];
    __shared__ float sred[8];
    int r = blockIdx.x, t = threadIdx.x;

    sagg[t] = g_agg[r*CC + t];
    __syncthreads();

    float no = bon[t];
    const float4* sa4 = (const float4*)sagg;
#pragma unroll 1
    for (int k4 = 0; k4 < CC/4; k4++) {
        float4 av = sa4[k4]; int kk = 4*k4;
        no = fmaf(av.x, Won[(kk+0)*CC+t], no);
        no = fmaf(av.y, Won[(kk+1)*CC+t], no);
        no = fmaf(av.z, Won[(kk+2)*CC+t], no);
        no = fmaf(av.w, Won[(kk+3)*CC+t], no);
    }
    float pre = g_x1[r*CC + t] + no;

    float mean = blockSum(pre, sred, t) * (1.f/CC);
    float d = pre - mean;
    float var = blockSum(d*d, sred, t) * (1.f/CC);
    float x2 = d * rsqrtf(var + EPSF) * ln3_s[t] + ln3_b[t];
    sx2[t] = x2;
    __syncthreads();

    const float4* sx24 = (const float4*)sx2;
#pragma unroll 1
    for (int hb = 0; hb < 4; hb++) {
        int h = hb*CC + t;
        float a = b1[h];
#pragma unroll 1
        for (int k4 = 0; k4 < CC/4; k4++) {
            float4 xv = sx24[k4]; int kk = 4*k4;
            a = fmaf(xv.x, w1[(kk+0)*HID+h], a);
            a = fmaf(xv.y, w1[(kk+1)*HID+h], a);
            a = fmaf(xv.z, w1[(kk+2)*HID+h], a);
            a = fmaf(xv.w, w1[(kk+3)*HID+h], a);
        }
        shid[h] = fmaxf(a, 0.f);
    }
    __syncthreads();

    float o = b2[t];
    const float4* sh4 = (const float4*)shid;
#pragma unroll 1
    for (int k4 = 0; k4 < HID/4; k4++) {
        float4 hv = sh4[k4]; int kk = 4*k4;
        o = fmaf(hv.x, w2[(kk+0)*CC+t], o);
        o = fmaf(hv.y, w2[(kk+1)*CC+t], o);
        o = fmaf(hv.z, w2[(kk+2)*CC+t], o);
        o = fmaf(hv.w, w2[(kk+3)*CC+t], o);
    }
    float pre2 = x2 + o;
    float mean2 = blockSum(pre2, sred, t) * (1.f/CC);
    float d2 = pre2 - mean2;
    float var2 = blockSum(d2*d2, sred, t) * (1.f/CC);
    xout[r*CC + t] = d2 * rsqrtf(var2 + EPSF) * ln5_s[t] + ln5_b[t];
}

// ---------------- K6f: fused edge MLP + LN6 (B reg-prefetched) -------------
__global__ void __launch_bounds__(512, 1) k6f(
    const float* __restrict__ b1, const float* __restrict__ b2,
    const float* __restrict__ ln6_s, const float* __restrict__ ln6_b,
    float* __restrict__ yout)
{
    extern __shared__ __align__(16) char dsm[];
    uint32_t* sA = (uint32_t*)dsm;
    uint32_t* sB = sA + 128 * PA;
    float* ln = (float*)dsm;
    __shared__ float sb1[HID];
    __shared__ float sb2[CC];

    int t = threadIdx.x, lane = t & 31, wid = t >> 5;
    int m0 = (wid & 3) * 32, n0 = (wid >> 2) * 64;
    int g = lane >> 2, tig = lane & 3;
    int tile = blockIdx.x;
    size_t base = (size_t)tile * 128;

    sb1[t] = b1[t]; sb1[t + 512] = b1[t + 512];
    if (t < CC) sb2[t] = b2[t];
    stageA(sA, g_y2, base, CC, 0, t);
    float4 pB[8];
    ldgB4(pB, g_w1T, CC, 0, t);
    __syncthreads();

    // ======== phase 1: hid = relu(y2 @ w1 + b1), 4 N-chunks ================
#pragma unroll 1
    for (int nc = 0; nc < 4; nc++) {
        float acc[2][8][4];
        initacc(acc, sb1 + nc * CC, n0, tig);
#pragma unroll 1
        for (int kc = 0; kc < 4; kc++) {
            stsB4(sB, pB, t);
            int nxt = nc * 4 + kc + 1;
            if (nxt < 16)
                ldgB4(pB, g_w1T + (size_t)(nxt >> 2) * CC * CC, CC,
                      (nxt & 3) * 64, t);
            __syncthreads();
            gemm64(sA + kc * 64, sB, acc, m0, n0, g, tig);
            __syncthreads();
        }

#pragma unroll
        for (int mf = 0; mf < 2; mf++)
#pragma unroll
            for (int nf = 0; nf < 8; nf++) {
                int r = m0 + mf * 16 + g;
                int c = nc * CC + n0 + nf * 8 + 2 * tig;
#pragma unroll
                for (int h = 0; h < 2; h++) {
                    int rr = r + 8 * h;
                    float2 o;
                    o.x = fmaxf(acc[mf][nf][2*h],   0.f);
                    o.y = fmaxf(acc[mf][nf][2*h+1], 0.f);
                    *(float2*)(g_hid + (base + rr) * HID + c) = o;
                }
            }
    }

    // ======== phase 2: out = hid @ w2 + b2 + y2 ; LN6 ======================
    ldgB4(pB, g_w2T, HID, 0, t);
    float acc[2][8][4];
    initacc(acc, sb2, n0, tig);

#pragma unroll 1
    for (int cc = 0; cc < 16; cc++) {
        if ((cc & 3) == 0) {
            __syncthreads();         // prior gemm done with sA; hid visible
            stageA(sA, g_hid, base, HID, (cc >> 2) * 256, t);
        }
        stsB4(sB, pB, t);
        if (cc < 15) ldgB4(pB, g_w2T, HID, (cc + 1) * 64, t);
        __syncthreads();             // sA (if restaged) + sB ready
        gemm64(sA + (cc & 3) * 64, sB, acc, m0, n0, g, tig);
        __syncthreads();
    }

#pragma unroll
    for (int mf = 0; mf < 2; mf++)
#pragma unroll
        for (int nf = 0; nf < 8; nf++) {
            int r = m0 + mf * 16 + g;
            int c = n0 + nf * 8 + 2 * tig;
#pragma unroll
            for (int h = 0; h < 2; h++) {
                int rr = r + 8 * h;
                float2 yv = *(const float2*)(g_y2 + (base + rr) * CC + c);
                float2 o;
                o.x = acc[mf][nf][2*h]   + yv.x;
                o.y = acc[mf][nf][2*h+1] + yv.y;
                *(float2*)(ln + rr * PA + c) = o;
            }
        }
    __syncthreads();

    ln_rows128(ln, yout, base, ln6_s, ln6_b, t);
}

// ---------------- launch ---------------------------------------------------
extern "C" void kernel_launch(void* const* d_in, const int* in_sizes, int n_in,
                              void* d_out, int out_size)
{
    const float* x   = (const float*)d_in[0];
    const float* y   = (const float*)d_in[1];
    const float* Wq  = (const float*)d_in[2];
    const float* bq  = (const float*)d_in[3];
    const float* Wk  = (const float*)d_in[4];
    const float* bk  = (const float*)d_in[5];
    const float* Wv  = (const float*)d_in[6];
    const float* bv  = (const float*)d_in[7];
    const float* We  = (const float*)d_in[8];
    const float* be  = (const float*)d_in[9];
    const float* Woe = (const float*)d_in[10];
    const float* boe = (const float*)d_in[11];
    const float* Won = (const float*)d_in[12];
    const float* bon = (const float*)d_in[13];
    const float* m1w1 = (const float*)d_in[14];
    const float* m1b1 = (const float*)d_in[15];
    const float* m1w2 = (const float*)d_in[16];
    const float* m1b2 = (const float*)d_in[17];
    const float* m2w1 = (const float*)d_in[18];
    const float* m2b1 = (const float*)d_in[19];
    const float* m2w2 = (const float*)d_in[20];
    const float* m2b2 = (const float*)d_in[21];
    const float* ln1s = (const float*)d_in[22];
    const float* ln1b = (const float*)d_in[23];
    const float* ln3s = (const float*)d_in[24];
    const float* ln3b = (const float*)d_in[25];
    const float* ln4s = (const float*)d_in[26];
    const float* ln4b = (const float*)d_in[27];
    const float* ln5s = (const float*)d_in[28];
    const float* ln5b = (const float*)d_in[29];
    const float* ln6s = (const float*)d_in[30];
    const float* ln6b = (const float*)d_in[31];

    float* xout = (float*)d_out;                   // (8,128,256)
    float* yout = (float*)d_out + ROWS*CC;         // (8,128,128,256)

    cudaFuncSetAttribute(k23, cudaFuncAttributeMaxDynamicSharedMemorySize, DSMEM);
    cudaFuncSetAttribute(k6f, cudaFuncAttributeMaxDynamicSharedMemorySize, DSMEM);

    ktrans<<<dim3(8, 8),  dim3(32, 8)>>>(We,   CC,  CC,  0);
    ktrans<<<dim3(8, 8),  dim3(32, 8)>>>(Woe,  CC,  CC,  1);
    ktrans<<<dim3(32, 8), dim3(32, 8)>>>(m2w1, CC,  HID, 2);
    ktrans<<<dim3(8, 32), dim3(32, 8)>>>(m2w2, HID, CC,  3);

    k1_node_qkv<<<ROWS, 256>>>(x, Wq, bq, Wk, bk, Wv, bv, ln1s, ln1b);
    k23<<<ROWS, 512, DSMEM>>>(y, be, boe, ln4s, ln4b);
    k5_node_mlp<<<ROWS, 256>>>(Won, bon, m1w1, m1b1, m1w2, m1b2,
                               ln3s, ln3b, ln5s, ln5b, xout);
    k6f<<<ROWS, 512, DSMEM>>>(m2b1, m2b2, ln6s, ln6b, yout);
}

// round 13
// speedup vs baseline: 4.6264x; 1.5091x over previous
#include <cuda_runtime.h>
#include <cuda_fp16.h>
#include <math.h>
#include <stdint.h>

#define BB   8
#define NN   128
#define CC   256
#define HID  1024
#define EPSF 1e-5f
#define ROWS (BB*NN)          /* 1024  */
#define EDGES (BB*NN*NN)      /* 131072 */
#define PA   260              /* LN overlay pitch in floats */
#define PAU  132              /* A smem pitch in u32 (half2) ; 132%32==4 */
#define PBU  36               /* B smem pitch in u32 (half2) ; 36%32==4  */

// ---------------- scratch (device globals; no allocation anywhere) ---------
__device__ float g_x1[ROWS*CC];
__device__ float g_q [ROWS*CC];
__device__ float g_k [ROWS*CC];
__device__ float g_v [ROWS*CC];
__device__ float g_agg[ROWS*CC];
__device__ float g_y2 [(size_t)EDGES*CC];     // 134 MB
__device__ float g_hid[(size_t)EDGES*HID];    // 512 MB (CTA-local, L2-hot)
__device__ float g_WeT [CC*CC];               // [n][k]
__device__ float g_WoeT[CC*CC];
__device__ float g_w1T [HID*CC];              // [h][k]
__device__ float g_w2T [CC*HID];              // [n][k]

// ---------------- fp16 mma helpers -----------------------------------------
__device__ __forceinline__ uint32_t f2h2(float lo, float hi) {
    uint32_t r;
    asm("cvt.rn.f16x2.f32 %0, %1, %2;" : "=r"(r) : "f"(hi), "f"(lo));
    return r;
}
__device__ __forceinline__ void mma16(float* c, const uint32_t a[4],
                                      uint32_t b0, uint32_t b1) {
    asm volatile("mma.sync.aligned.m16n8k16.row.col.f32.f16.f16.f32 "
        "{%0,%1,%2,%3}, {%4,%5,%6,%7}, {%8,%9}, {%0,%1,%2,%3};"
        : "+f"(c[0]), "+f"(c[1]), "+f"(c[2]), "+f"(c[3])
        : "r"(a[0]), "r"(a[1]), "r"(a[2]), "r"(a[3]), "r"(b0), "r"(b1));
}

// stage A tile (128 x 256 floats) -> smem half2, pitch PAU. 512 threads.
__device__ __forceinline__ void stageAh(uint32_t* __restrict__ sA,
                                        const float* __restrict__ src,
                                        size_t row0, int ld, int k0, int t) {
#pragma unroll
    for (int i = 0; i < 16; i++) {
        int f = t + 512 * i;
        int m = f >> 6, k = (f & 63) * 4;
        float4 v = *(const float4*)(src + (row0 + m) * (size_t)ld + k0 + k);
        uint2 u;
        u.x = f2h2(v.x, v.y); u.y = f2h2(v.z, v.w);
        *(uint2*)(sA + m * PAU + (k >> 1)) = u;
    }
}
// prefetch B chunk (256 n x 64 k floats) into registers. 512 threads.
__device__ __forceinline__ void ldgB4(float4* __restrict__ pB,
                                      const float* __restrict__ W,
                                      int ld, int k0, int t) {
#pragma unroll
    for (int i = 0; i < 8; i++) {
        int f = t + 512 * i;
        int n = f >> 4, k = (f & 15) * 4;
        pB[i] = *(const float4*)(W + (size_t)n * ld + k0 + k);
    }
}
// store prefetched B regs -> smem half2, pitch PBU.
__device__ __forceinline__ void stsB4h(uint32_t* __restrict__ sB,
                                       const float4* __restrict__ pB, int t) {
#pragma unroll
    for (int i = 0; i < 8; i++) {
        int f = t + 512 * i;
        int n = f >> 4, k = (f & 15) * 4;
        uint2 u;
        u.x = f2h2(pB[i].x, pB[i].y); u.y = f2h2(pB[i].z, pB[i].w);
        *(uint2*)(sB + n * PBU + (k >> 1)) = u;
    }
}
// one K=64 chunk = 4 x m16n8k16. Pass sA pre-offset (u32 units) to chunk.
__device__ __forceinline__ void gemm64h(const uint32_t* __restrict__ sA,
                                        const uint32_t* __restrict__ sB,
                                        float acc[2][8][4],
                                        int m0, int n0, int g, int tig) {
#pragma unroll
    for (int ks = 0; ks < 4; ks++) {
        int k0 = ks * 8;                       // 8 u32 = 16 halves = K16
        uint32_t af[2][4];
#pragma unroll
        for (int mf = 0; mf < 2; mf++) {
            int r = m0 + mf * 16 + g;
            af[mf][0] = sA[r * PAU + k0 + tig];
            af[mf][1] = sA[(r + 8) * PAU + k0 + tig];
            af[mf][2] = sA[r * PAU + k0 + tig + 4];
            af[mf][3] = sA[(r + 8) * PAU + k0 + tig + 4];
        }
#pragma unroll
        for (int nf = 0; nf < 8; nf++) {
            int n = n0 + nf * 8 + g;
            uint32_t b0 = sB[n * PBU + k0 + tig];
            uint32_t b1 = sB[n * PBU + k0 + tig + 4];
            mma16(acc[0][nf], af[0], b0, b1);
            mma16(acc[1][nf], af[1], b0, b1);
        }
    }
}
__device__ __forceinline__ void initacc(float acc[2][8][4],
                                        const float* sbias, int n0, int tig) {
#pragma unroll
    for (int mf = 0; mf < 2; mf++)
#pragma unroll
        for (int nf = 0; nf < 8; nf++) {
            int c = n0 + nf * 8 + 2 * tig;
            acc[mf][nf][0] = acc[mf][nf][2] = sbias[c];
            acc[mf][nf][1] = acc[mf][nf][3] = sbias[c + 1];
        }
}

// ---------------- misc fp32 helpers ----------------------------------------
__device__ __forceinline__ float warpSum(float v) {
#pragma unroll
    for (int o = 16; o > 0; o >>= 1) v += __shfl_xor_sync(0xffffffffu, v, o);
    return v;
}
__device__ __forceinline__ float blockSum(float v, float* sred, int t) {
    v = warpSum(v);
    __syncthreads();
    if ((t & 31) == 0) sred[t >> 5] = v;
    __syncthreads();
    float tot = 0.f;
#pragma unroll
    for (int w = 0; w < 8; w++) tot += sred[w];
    return tot;
}
// LN over 128 rows x 256 cols in ln[r*PA + c] (512 threads)
__device__ __forceinline__ void ln_rows128(const float* ln, float* __restrict__ out,
                                           size_t base, const float* __restrict__ s,
                                           const float* __restrict__ bsh, int t) {
    int w = t >> 5, l = t & 31;
#pragma unroll 1
    for (int u = 0; u < 8; u++) {
        int r = u * 16 + w;
        float sm = 0.f, sq = 0.f;
#pragma unroll
        for (int c0 = 0; c0 < CC; c0 += 32) {
            float v = ln[r * PA + c0 + l];
            sm += v; sq = fmaf(v, v, sq);
        }
        sm = warpSum(sm); sq = warpSum(sq);
        float mean = sm * (1.f / CC);
        float rstd = rsqrtf(sq * (1.f / CC) - mean * mean + EPSF);
#pragma unroll
        for (int c0 = 0; c0 < CC; c0 += 32) {
            int c = c0 + l;
            out[(base + r) * CC + c] = (ln[r * PA + c] - mean) * rstd * s[c] + bsh[c];
        }
    }
}

// ---------------- weight transpose -----------------------------------------
__global__ void ktrans(const float* __restrict__ src, int R, int Cc, int which) {
    float* dst = which == 0 ? g_WeT : which == 1 ? g_WoeT
               : which == 2 ? g_w1T : g_w2T;
    __shared__ float tb[32][33];
    int bx = blockIdx.x * 32, by = blockIdx.y * 32;
    int tx = threadIdx.x, ty = threadIdx.y;
#pragma unroll
    for (int i = 0; i < 32; i += 8)
        tb[ty + i][tx] = src[(size_t)(by + ty + i) * Cc + bx + tx];
    __syncthreads();
#pragma unroll
    for (int i = 0; i < 32; i += 8)
        dst[(size_t)(bx + ty + i) * R + by + tx] = tb[tx][ty + i];
}

// ---------------- K1: LN1 + qkv --------------------------------------------
__global__ void __launch_bounds__(256) k1_node_qkv(
    const float* __restrict__ x,
    const float* __restrict__ Wq, const float* __restrict__ bq,
    const float* __restrict__ Wk, const float* __restrict__ bk,
    const float* __restrict__ Wv, const float* __restrict__ bv,
    const float* __restrict__ ln1_s, const float* __restrict__ ln1_b)
{
    __shared__ __align__(16) float sx[CC];
    __shared__ float sred[8];
    int r = blockIdx.x, t = threadIdx.x;

    float xv = x[r*CC + t];
    float mean = blockSum(xv, sred, t) * (1.f/CC);
    float d = xv - mean;
    float var = blockSum(d*d, sred, t) * (1.f/CC);
    float x1 = d * rsqrtf(var + EPSF) * ln1_s[t] + ln1_b[t];
    sx[t] = x1;
    g_x1[r*CC + t] = x1;
    __syncthreads();

    float aq = bq[t], ak = bk[t], av = bv[t];
    const float4* sx4 = (const float4*)sx;
#pragma unroll 1
    for (int k4 = 0; k4 < CC/4; k4++) {
        float4 v = sx4[k4]; int kk = 4*k4;
        aq = fmaf(v.x, Wq[(kk+0)*CC+t], aq);
        aq = fmaf(v.y, Wq[(kk+1)*CC+t], aq);
        aq = fmaf(v.z, Wq[(kk+2)*CC+t], aq);
        aq = fmaf(v.w, Wq[(kk+3)*CC+t], aq);
        ak = fmaf(v.x, Wk[(kk+0)*CC+t], ak);
        ak = fmaf(v.y, Wk[(kk+1)*CC+t], ak);
        ak = fmaf(v.z, Wk[(kk+2)*CC+t], ak);
        ak = fmaf(v.w, Wk[(kk+3)*CC+t], ak);
        av = fmaf(v.x, Wv[(kk+0)*CC+t], av);
        av = fmaf(v.y, Wv[(kk+1)*CC+t], av);
        av = fmaf(v.z, Wv[(kk+2)*CC+t], av);
        av = fmaf(v.w, Wv[(kk+3)*CC+t], av);
    }
    g_q[r*CC+t] = aq;  g_k[r*CC+t] = ak;  g_v[r*CC+t] = av;
}

// A(128*PAU) + 2x B(256*PBU) in u32; LN overlay needs 128*PA floats
#define DSMEM ((128*PAU + 2*256*PBU) * 4)   /* 141,312 B >= 133,120 LN */

// ---------------- K23: e-proj + attn + softmax-agg + edge_out + LN4 --------
__global__ void __launch_bounds__(512, 1) k23(
    const float* __restrict__ y, const float* __restrict__ be,
    const float* __restrict__ boe,
    const float* __restrict__ ln4_s, const float* __restrict__ ln4_b)
{
    extern __shared__ __align__(16) char dsm[];
    uint32_t* sA  = (uint32_t*)dsm;
    uint32_t* sB0 = sA + 128 * PAU;
    uint32_t* sB1 = sB0 + 256 * PBU;
    float* ln = (float*)dsm;
    __shared__ float s_q[CC], s_bb[CC], s_b2[CC];

    int t = threadIdx.x, lane = t & 31, wid = t >> 5;
    int m0 = (wid & 3) * 32, n0 = (wid >> 2) * 64;
    int g = lane >> 2, tig = lane & 3;
    int tile = blockIdx.x;
    size_t base = (size_t)tile * 128;
    int krow = (tile >> 7) << 7;

    if (t < CC) {
        s_bb[t] = be[t];
        s_b2[t] = boe[t];
        s_q[t]  = g_q[(size_t)tile*CC + t] * 0.17677669529663687f;  // 1/sqrt(32)
    }
    stageAh(sA, y, base, CC, 0, t);
    float4 pB[8];
    ldgB4(pB, g_WeT, CC, 0, t);
    __syncthreads();                 // sA + s_* ready

    // ---- GEMM1: e = y @ We + be (double-buffered sB, 1 sync/chunk) --------
    float acc[2][8][4];
    initacc(acc, s_bb, n0, tig);
#pragma unroll 1
    for (int kc = 0; kc < 4; kc++) {
        stsB4h((kc & 1) ? sB1 : sB0, pB, t);
        if (kc < 3) ldgB4(pB, g_WeT, CC, (kc + 1) * 64, t);
        __syncthreads();
        gemm64h(sA + kc * 32, (kc & 1) ? sB1 : sB0, acc, m0, n0, g, tig);
    }
    ldgB4(pB, g_WoeT, CC, 0, t);     // prefetch GEMM2 chunk0
    __syncthreads();                 // all warps done reading sA

    // ---- epilogue1: attn = q*k/sqrt(dk)*(e+1)*e -> half2 into sA ----------
#pragma unroll
    for (int mf = 0; mf < 2; mf++)
#pragma unroll
        for (int nf = 0; nf < 8; nf++) {
            int r = m0 + mf * 16 + g;
            int c = n0 + nf * 8 + 2 * tig;
#pragma unroll
            for (int h = 0; h < 2; h++) {
                int rr = r + 8 * h;
                float e0 = acc[mf][nf][2*h], e1 = acc[mf][nf][2*h+1];
                float2 kv = *(const float2*)(g_k + (size_t)(krow + rr) * CC + c);
                float a0 = s_q[c]   * kv.x * (e0 + 1.f) * e0;
                float a1 = s_q[c+1] * kv.y * (e1 + 1.f) * e1;
                sA[rr * PAU + (c >> 1)] = f2h2(a0, a1);
            }
        }
    __syncthreads();                 // attn tile visible

    // ---- fused softmax over j + V aggregation (tile-local) ----------------
    {
        float* red = (float*)sB0;    // 1536 floats of partials
        int c = t & 255, half = t >> 8;
        const float* vp = g_v + (size_t)(krow + half * 64) * CC + c;
        float m = -3.4e38f, s = 0.f, a = 0.f;
#pragma unroll 4
        for (int j = 0; j < 64; j++) {
            uint32_t u = sA[(half * 64 + j) * PAU + (c >> 1)];
            float2 h2 = __half22float2(*(const __half2*)&u);
            float av = (c & 1) ? h2.y : h2.x;
            float nm = fmaxf(m, av);
            float corr = __expf(m - nm);
            float p = __expf(av - nm);
            s = s * corr + p;
            a = a * corr + p * vp[(size_t)j * CC];
            m = nm;
        }
        red[half * 256 + c]        = m;
        red[512 + half * 256 + c]  = s;
        red[1024 + half * 256 + c] = a;
        __syncthreads();
        if (t < 256) {
            float m0_ = red[c],       m1_ = red[256 + c];
            float s0  = red[512 + c], s1  = red[768 + c];
            float a0  = red[1024 + c], a1 = red[1280 + c];
            float mm = fmaxf(m0_, m1_);
            float e0 = __expf(m0_ - mm), e1 = __expf(m1_ - mm);
            g_agg[(size_t)tile * CC + c] = (a0 * e0 + a1 * e1) / (s0 * e0 + s1 * e1);
        }
    }
    __syncthreads();                 // red reads done; sB free

    // ---- GEMM2: edge_out = attn @ Woe + boe -------------------------------
    initacc(acc, s_b2, n0, tig);
#pragma unroll 1
    for (int kc = 0; kc < 4; kc++) {
        stsB4h((kc & 1) ? sB1 : sB0, pB, t);
        if (kc < 3) ldgB4(pB, g_WoeT, CC, (kc + 1) * 64, t);
        __syncthreads();
        gemm64h(sA + kc * 32, (kc & 1) ? sB1 : sB0, acc, m0, n0, g, tig);
    }
    __syncthreads();                 // gemm reads done; ln overlay safe

    // ---- epilogue2: + y residual -> ln buffer -> LN4 -> g_y2 --------------
#pragma unroll
    for (int mf = 0; mf < 2; mf++)
#pragma unroll
        for (int nf = 0; nf < 8; nf++) {
            int r = m0 + mf * 16 + g;
            int c = n0 + nf * 8 + 2 * tig;
#pragma unroll
            for (int h = 0; h < 2; h++) {
                int rr = r + 8 * h;
                float2 yv = *(const float2*)(y + (base + rr) * CC + c);
                float2 o;
                o.x = acc[mf][nf][2*h]   + yv.x;
                o.y = acc[mf][nf][2*h+1] + yv.y;
                *(float2*)(ln + rr * PA + c) = o;
            }
        }
    __syncthreads();

    ln_rows128(ln, g_y2, base, ln4_s, ln4_b, t);
}

// ---------------- K5: node out proj + LN3 + MLP + LN5 ----------------------
__global__ void __launch_bounds__(256) k5_node_mlp(
    const float* __restrict__ Won, const float* __restrict__ bon,
    const float* __restrict__ w1, const float* __restrict__ b1,
    const float* __restrict__ w2, const float* __restrict__ b2,
    const float* __restrict__ ln3_s, const float* __restrict__ ln3_b,
    const float* __restrict__ ln5_s, const float* __restrict__ ln5_b,
    float* __restrict__ xout)
{
    __shared__ __align__(16) float sagg[CC];
    __shared__ __align__(16) float sx2[CC];
    __shared__ __align__(16) float shid[HID];
    __shared__ float sred[8];
    int r = blockIdx.x, t = threadIdx.x;

    sagg[t] = g_agg[r*CC + t];
    __syncthreads();

    float no = bon[t];
    const float4* sa4 = (const float4*)sagg;
#pragma unroll 1
    for (int k4 = 0; k4 < CC/4; k4++) {
        float4 av = sa4[k4]; int kk = 4*k4;
        no = fmaf(av.x, Won[(kk+0)*CC+t], no);
        no = fmaf(av.y, Won[(kk+1)*CC+t], no);
        no = fmaf(av.z, Won[(kk+2)*CC+t], no);
        no = fmaf(av.w, Won[(kk+3)*CC+t], no);
    }
    float pre = g_x1[r*CC + t] + no;

    float mean = blockSum(pre, sred, t) * (1.f/CC);
    float d = pre - mean;
    float var = blockSum(d*d, sred, t) * (1.f/CC);
    float x2 = d * rsqrtf(var + EPSF) * ln3_s[t] + ln3_b[t];
    sx2[t] = x2;
    __syncthreads();

    const float4* sx24 = (const float4*)sx2;
#pragma unroll 1
    for (int hb = 0; hb < 4; hb++) {
        int h = hb*CC + t;
        float a = b1[h];
#pragma unroll 1
        for (int k4 = 0; k4 < CC/4; k4++) {
            float4 xv = sx24[k4]; int kk = 4*k4;
            a = fmaf(xv.x, w1[(kk+0)*HID+h], a);
            a = fmaf(xv.y, w1[(kk+1)*HID+h], a);
            a = fmaf(xv.z, w1[(kk+2)*HID+h], a);
            a = fmaf(xv.w, w1[(kk+3)*HID+h], a);
        }
        shid[h] = fmaxf(a, 0.f);
    }
    __syncthreads();

    float o = b2[t];
    const float4* sh4 = (const float4*)shid;
#pragma unroll 1
    for (int k4 = 0; k4 < HID/4; k4++) {
        float4 hv = sh4[k4]; int kk = 4*k4;
        o = fmaf(hv.x, w2[(kk+0)*CC+t], o);
        o = fmaf(hv.y, w2[(kk+1)*CC+t], o);
        o = fmaf(hv.z, w2[(kk+2)*CC+t], o);
        o = fmaf(hv.w, w2[(kk+3)*CC+t], o);
    }
    float pre2 = x2 + o;
    float mean2 = blockSum(pre2, sred, t) * (1.f/CC);
    float d2 = pre2 - mean2;
    float var2 = blockSum(d2*d2, sred, t) * (1.f/CC);
    xout[r*CC + t] = d2 * rsqrtf(var2 + EPSF) * ln5_s[t] + ln5_b[t];
}

// ---------------- K6f: fused edge MLP + LN6 (fp16 MMA) ---------------------
__global__ void __launch_bounds__(512, 1) k6f(
    const float* __restrict__ b1, const float* __restrict__ b2,
    const float* __restrict__ ln6_s, const float* __restrict__ ln6_b,
    float* __restrict__ yout)
{
    extern __shared__ __align__(16) char dsm[];
    uint32_t* sA  = (uint32_t*)dsm;
    uint32_t* sB0 = sA + 128 * PAU;
    uint32_t* sB1 = sB0 + 256 * PBU;
    float* ln = (float*)dsm;
    __shared__ float sb1[HID];
    __shared__ float sb2[CC];

    int t = threadIdx.x, lane = t & 31, wid = t >> 5;
    int m0 = (wid & 3) * 32, n0 = (wid >> 2) * 64;
    int g = lane >> 2, tig = lane & 3;
    int tile = blockIdx.x;
    size_t base = (size_t)tile * 128;

    sb1[t] = b1[t]; sb1[t + 512] = b1[t + 512];
    if (t < CC) sb2[t] = b2[t];
    stageAh(sA, g_y2, base, CC, 0, t);
    float4 pB[8];
    ldgB4(pB, g_w1T, CC, 0, t);
    __syncthreads();

    // ======== phase 1: hid = relu(y2 @ w1 + b1), 4 N-chunks ================
#pragma unroll 1
    for (int nc = 0; nc < 4; nc++) {
        float acc[2][8][4];
        initacc(acc, sb1 + nc * CC, n0, tig);
#pragma unroll 1
        for (int kc = 0; kc < 4; kc++) {
            int cgl = nc * 4 + kc;
            stsB4h((cgl & 1) ? sB1 : sB0, pB, t);
            int nxt = cgl + 1;
            if (nxt < 16)
                ldgB4(pB, g_w1T + (size_t)(nxt >> 2) * CC * CC, CC,
                      (nxt & 3) * 64, t);
            __syncthreads();
            gemm64h(sA + kc * 32, (cgl & 1) ? sB1 : sB0, acc, m0, n0, g, tig);
        }

#pragma unroll
        for (int mf = 0; mf < 2; mf++)
#pragma unroll
            for (int nf = 0; nf < 8; nf++) {
                int r = m0 + mf * 16 + g;
                int c = nc * CC + n0 + nf * 8 + 2 * tig;
#pragma unroll
                for (int h = 0; h < 2; h++) {
                    int rr = r + 8 * h;
                    float2 o;
                    o.x = fmaxf(acc[mf][nf][2*h],   0.f);
                    o.y = fmaxf(acc[mf][nf][2*h+1], 0.f);
                    *(float2*)(g_hid + (base + rr) * HID + c) = o;
                }
            }
    }

    // ======== phase 2: out = hid @ w2 + b2 + y2 ; LN6 ======================
    ldgB4(pB, g_w2T, HID, 0, t);
    float acc[2][8][4];
    initacc(acc, sb2, n0, tig);

#pragma unroll 1
    for (int cc = 0; cc < 16; cc++) {
        if ((cc & 3) == 0) {
            __syncthreads();         // prior gemm done with sA; hid visible
            stageAh(sA, g_hid, base, HID, (cc >> 2) * 256, t);
        }
        stsB4h((cc & 1) ? sB1 : sB0, pB, t);
        if (cc < 15) ldgB4(pB, g_w2T, HID, (cc + 1) * 64, t);
        __syncthreads();             // sA (if restaged) + sB ready
        gemm64h(sA + (cc & 3) * 32, (cc & 1) ? sB1 : sB0, acc, m0, n0, g, tig);
    }
    __syncthreads();                 // gemm reads done; ln overlay safe

#pragma unroll
    for (int mf = 0; mf < 2; mf++)
#pragma unroll
        for (int nf = 0; nf < 8; nf++) {
            int r = m0 + mf * 16 + g;
            int c = n0 + nf * 8 + 2 * tig;
#pragma unroll
            for (int h = 0; h < 2; h++) {
                int rr = r + 8 * h;
                float2 yv = *(const float2*)(g_y2 + (base + rr) * CC + c);
                float2 o;
                o.x = acc[mf][nf][2*h]   + yv.x;
                o.y = acc[mf][nf][2*h+1] + yv.y;
                *(float2*)(ln + rr * PA + c) = o;
            }
        }
    __syncthreads();

    ln_rows128(ln, yout, base, ln6_s, ln6_b, t);
}

// ---------------- launch ---------------------------------------------------
extern "C" void kernel_launch(void* const* d_in, const int* in_sizes, int n_in,
                              void* d_out, int out_size)
{
    const float* x   = (const float*)d_in[0];
    const float* y   = (const float*)d_in[1];
    const float* Wq  = (const float*)d_in[2];
    const float* bq  = (const float*)d_in[3];
    const float* Wk  = (const float*)d_in[4];
    const float* bk  = (const float*)d_in[5];
    const float* Wv  = (const float*)d_in[6];
    const float* bv  = (const float*)d_in[7];
    const float* We  = (const float*)d_in[8];
    const float* be  = (const float*)d_in[9];
    const float* Woe = (const float*)d_in[10];
    const float* boe = (const float*)d_in[11];
    const float* Won = (const float*)d_in[12];
    const float* bon = (const float*)d_in[13];
    const float* m1w1 = (const float*)d_in[14];
    const float* m1b1 = (const float*)d_in[15];
    const float* m1w2 = (const float*)d_in[16];
    const float* m1b2 = (const float*)d_in[17];
    const float* m2w1 = (const float*)d_in[18];
    const float* m2b1 = (const float*)d_in[19];
    const float* m2w2 = (const float*)d_in[20];
    const float* m2b2 = (const float*)d_in[21];
    const float* ln1s = (const float*)d_in[22];
    const float* ln1b = (const float*)d_in[23];
    const float* ln3s = (const float*)d_in[24];
    const float* ln3b = (const float*)d_in[25];
    const float* ln4s = (const float*)d_in[26];
    const float* ln4b = (const float*)d_in[27];
    const float* ln5s = (const float*)d_in[28];
    const float* ln5b = (const float*)d_in[29];
    const float* ln6s = (const float*)d_in[30];
    const float* ln6b = (const float*)d_in[31];

    float* xout = (float*)d_out;                   // (8,128,256)
    float* yout = (float*)d_out + ROWS*CC;         // (8,128,128,256)

    cudaFuncSetAttribute(k23, cudaFuncAttributeMaxDynamicSharedMemorySize, DSMEM);
    cudaFuncSetAttribute(k6f, cudaFuncAttributeMaxDynamicSharedMemorySize, DSMEM);

    ktrans<<<dim3(8, 8),  dim3(32, 8)>>>(We,   CC,  CC,  0);
    ktrans<<<dim3(8, 8),  dim3(32, 8)>>>(Woe,  CC,  CC,  1);
    ktrans<<<dim3(32, 8), dim3(32, 8)>>>(m2w1, CC,  HID, 2);
    ktrans<<<dim3(8, 32), dim3(32, 8)>>>(m2w2, HID, CC,  3);

    k1_node_qkv<<<ROWS, 256>>>(x, Wq, bq, Wk, bk, Wv, bv, ln1s, ln1b);
    k23<<<ROWS, 512, DSMEM>>>(y, be, boe, ln4s, ln4b);
    k5_node_mlp<<<ROWS, 256>>>(Won, bon, m1w1, m1b1, m1w2, m1b2,
                               ln3s, ln3b, ln5s, ln5b, xout);
    k6f<<<ROWS, 512, DSMEM>>>(m2b1, m2b2, ln6s, ln6b, yout);
}

// round 15
// speedup vs baseline: 4.9448x; 1.0688x over previous
#include <cuda_runtime.h>
#include <cuda_fp16.h>
#include <math.h>
#include <stdint.h>

#define BB   8
#define NN   128
#define CC   256
#define HID  1024
#define EPSF 1e-5f
#define ROWS (BB*NN)          /* 1024  */
#define EDGES (BB*NN*NN)      /* 131072 */
#define PA   260              /* LN overlay pitch in floats */
#define PAU  132              /* A smem pitch in u32 (half2) ; 132%32==4 */
#define PBU  36               /* B smem pitch in u32 (half2) ; 36%32==4  */

// ---------------- scratch (device globals; no allocation anywhere) ---------
__device__ float g_x1[ROWS*CC];
__device__ float g_q [ROWS*CC];
__device__ float g_k [ROWS*CC];
__device__ float g_v [ROWS*CC];
__device__ float g_agg[ROWS*CC];
__device__ float g_y2 [(size_t)EDGES*CC];           // 134 MB
__device__ uint32_t g_hidh[(size_t)EDGES*HID/2];    // 256 MB half2
__device__ __half g_WeTh [CC*CC];                   // [n][k] half
__device__ __half g_WoeTh[CC*CC];
__device__ __half g_w1Th [HID*CC];                  // [h][k]
__device__ __half g_w2Th [CC*HID];                  // [n][k]

// ---------------- fp16 mma helpers -----------------------------------------
__device__ __forceinline__ uint32_t f2h2(float lo, float hi) {
    uint32_t r;
    asm("cvt.rn.f16x2.f32 %0, %1, %2;" : "=r"(r) : "f"(hi), "f"(lo));
    return r;
}
__device__ __forceinline__ void mma16(float* c, const uint32_t a[4],
                                      uint32_t b0, uint32_t b1) {
    asm volatile("mma.sync.aligned.m16n8k16.row.col.f32.f16.f16.f32 "
        "{%0,%1,%2,%3}, {%4,%5,%6,%7}, {%8,%9}, {%0,%1,%2,%3};"
        : "+f"(c[0]), "+f"(c[1]), "+f"(c[2]), "+f"(c[3])
        : "r"(a[0]), "r"(a[1]), "r"(a[2]), "r"(a[3]), "r"(b0), "r"(b1));
}

// stage A tile (128 x 256 floats) -> smem half2, pitch PAU. 512 threads.
__device__ __forceinline__ void stageAh(uint32_t* __restrict__ sA,
                                        const float* __restrict__ src,
                                        size_t row0, int ld, int k0, int t) {
#pragma unroll
    for (int i = 0; i < 16; i++) {
        int f = t + 512 * i;
        int m = f >> 6, k = (f & 63) * 4;
        float4 v = *(const float4*)(src + (row0 + m) * (size_t)ld + k0 + k);
        uint2 u;
        u.x = f2h2(v.x, v.y); u.y = f2h2(v.z, v.w);
        *(uint2*)(sA + m * PAU + (k >> 1)) = u;
    }
}
// copy A tile (128 x 256 halves) from half2 global -> smem, no cvt.
__device__ __forceinline__ void stageAcpy(uint32_t* __restrict__ sA,
                                          const uint32_t* __restrict__ srcH,
                                          size_t row0, int k0u, int t) {
#pragma unroll
    for (int i = 0; i < 8; i++) {
        int f = t + 512 * i;
        int m = f >> 5, j = f & 31;
        *(uint4*)(sA + m * PAU + j * 4) =
            *(const uint4*)(srcH + (row0 + m) * (size_t)(HID/2) + k0u + j * 4);
    }
}
// prefetch B chunk (256 n x 64 k halves) into registers. 512 threads.
__device__ __forceinline__ void ldgBh(uint4* __restrict__ pB,
                                      const __half* __restrict__ Wh,
                                      int ldh, int k0h, int t) {
#pragma unroll
    for (int i = 0; i < 4; i++) {
        int f = t + 512 * i;
        int n = f >> 3, j = f & 7;
        pB[i] = *(const uint4*)(Wh + (size_t)n * ldh + k0h + j * 8);
    }
}
// store prefetched half B regs -> smem, pitch PBU.
__device__ __forceinline__ void stsBh(uint32_t* __restrict__ sB,
                                      const uint4* __restrict__ pB, int t) {
#pragma unroll
    for (int i = 0; i < 4; i++) {
        int f = t + 512 * i;
        int n = f >> 3, j = f & 7;
        *(uint4*)(sB + n * PBU + j * 4) = pB[i];
    }
}
// one K=64 chunk = 4 x m16n8k16. Pass sA pre-offset (u32 units) to chunk.
__device__ __forceinline__ void gemm64h(const uint32_t* __restrict__ sA,
                                        const uint32_t* __restrict__ sB,
                                        float acc[2][8][4],
                                        int m0, int n0, int g, int tig) {
#pragma unroll
    for (int ks = 0; ks < 4; ks++) {
        int k0 = ks * 8;                       // 8 u32 = 16 halves = K16
        uint32_t af[2][4];
#pragma unroll
        for (int mf = 0; mf < 2; mf++) {
            int r = m0 + mf * 16 + g;
            af[mf][0] = sA[r * PAU + k0 + tig];
            af[mf][1] = sA[(r + 8) * PAU + k0 + tig];
            af[mf][2] = sA[r * PAU + k0 + tig + 4];
            af[mf][3] = sA[(r + 8) * PAU + k0 + tig + 4];
        }
#pragma unroll
        for (int nf = 0; nf < 8; nf++) {
            int n = n0 + nf * 8 + g;
            uint32_t b0 = sB[n * PBU + k0 + tig];
            uint32_t b1 = sB[n * PBU + k0 + tig + 4];
            mma16(acc[0][nf], af[0], b0, b1);
            mma16(acc[1][nf], af[1], b0, b1);
        }
    }
}
__device__ __forceinline__ void initacc(float acc[2][8][4],
                                        const float* sbias, int n0, int tig) {
#pragma unroll
    for (int mf = 0; mf < 2; mf++)
#pragma unroll
        for (int nf = 0; nf < 8; nf++) {
            int c = n0 + nf * 8 + 2 * tig;
            acc[mf][nf][0] = acc[mf][nf][2] = sbias[c];
            acc[mf][nf][1] = acc[mf][nf][3] = sbias[c + 1];
        }
}

// ---------------- misc fp32 helpers ----------------------------------------
__device__ __forceinline__ float warpSum(float v) {
#pragma unroll
    for (int o = 16; o > 0; o >>= 1) v += __shfl_xor_sync(0xffffffffu, v, o);
    return v;
}
__device__ __forceinline__ float blockSum(float v, float* sred, int t) {
    v = warpSum(v);
    __syncthreads();
    if ((t & 31) == 0) sred[t >> 5] = v;
    __syncthreads();
    float tot = 0.f;
#pragma unroll
    for (int w = 0; w < 8; w++) tot += sred[w];
    return tot;
}
// LN over 128 rows x 256 cols in ln[r*PA + c] (512 threads)
__device__ __forceinline__ void ln_rows128(const float* ln, float* __restrict__ out,
                                           size_t base, const float* __restrict__ s,
                                           const float* __restrict__ bsh, int t) {
    int w = t >> 5, l = t & 31;
#pragma unroll 1
    for (int u = 0; u < 8; u++) {
        int r = u * 16 + w;
        float sm = 0.f, sq = 0.f;
#pragma unroll
        for (int c0 = 0; c0 < CC; c0 += 32) {
            float v = ln[r * PA + c0 + l];
            sm += v; sq = fmaf(v, v, sq);
        }
        sm = warpSum(sm); sq = warpSum(sq);
        float mean = sm * (1.f / CC);
        float rstd = rsqrtf(sq * (1.f / CC) - mean * mean + EPSF);
#pragma unroll
        for (int c0 = 0; c0 < CC; c0 += 32) {
            int c = c0 + l;
            out[(base + r) * CC + c] = (ln[r * PA + c] - mean) * rstd * s[c] + bsh[c];
        }
    }
}

// ---------------- weight transpose -> half ---------------------------------
__global__ void ktrans(const float* __restrict__ src, int R, int Cc, int which) {
    __half* dst = which == 0 ? g_WeTh : which == 1 ? g_WoeTh
                : which == 2 ? g_w1Th : g_w2Th;
    __shared__ float tb[32][33];
    int bx = blockIdx.x * 32, by = blockIdx.y * 32;
    int tx = threadIdx.x, ty = threadIdx.y;
#pragma unroll
    for (int i = 0; i < 32; i += 8)
        tb[ty + i][tx] = src[(size_t)(by + ty + i) * Cc + bx + tx];
    __syncthreads();
#pragma unroll
    for (int i = 0; i < 32; i += 8)
        dst[(size_t)(bx + ty + i) * R + by + tx] = __float2half(tb[tx][ty + i]);
}

// ---------------- K1: LN1 + qkv --------------------------------------------
__global__ void __launch_bounds__(256) k1_node_qkv(
    const float* __restrict__ x,
    const float* __restrict__ Wq, const float* __restrict__ bq,
    const float* __restrict__ Wk, const float* __restrict__ bk,
    const float* __restrict__ Wv, const float* __restrict__ bv,
    const float* __restrict__ ln1_s, const float* __restrict__ ln1_b)
{
    __shared__ __align__(16) float sx[CC];
    __shared__ float sred[8];
    int r = blockIdx.x, t = threadIdx.x;

    float xv = x[r*CC + t];
    float mean = blockSum(xv, sred, t) * (1.f/CC);
    float d = xv - mean;
    float var = blockSum(d*d, sred, t) * (1.f/CC);
    float x1 = d * rsqrtf(var + EPSF) * ln1_s[t] + ln1_b[t];
    sx[t] = x1;
    g_x1[r*CC + t] = x1;
    __syncthreads();

    float aq = bq[t], ak = bk[t], av = bv[t];
    const float4* sx4 = (const float4*)sx;
#pragma unroll 1
    for (int k4 = 0; k4 < CC/4; k4++) {
        float4 v = sx4[k4]; int kk = 4*k4;
        aq = fmaf(v.x, Wq[(kk+0)*CC+t], aq);
        aq = fmaf(v.y, Wq[(kk+1)*CC+t], aq);
        aq = fmaf(v.z, Wq[(kk+2)*CC+t], aq);
        aq = fmaf(v.w, Wq[(kk+3)*CC+t], aq);
        ak = fmaf(v.x, Wk[(kk+0)*CC+t], ak);
        ak = fmaf(v.y, Wk[(kk+1)*CC+t], ak);
        ak = fmaf(v.z, Wk[(kk+2)*CC+t], ak);
        ak = fmaf(v.w, Wk[(kk+3)*CC+t], ak);
        av = fmaf(v.x, Wv[(kk+0)*CC+t], av);
        av = fmaf(v.y, Wv[(kk+1)*CC+t], av);
        av = fmaf(v.z, Wv[(kk+2)*CC+t], av);
        av = fmaf(v.w, Wv[(kk+3)*CC+t], av);
    }
    g_q[r*CC+t] = aq;  g_k[r*CC+t] = ak;  g_v[r*CC+t] = av;
}

// A(128*PAU) + 2x B(256*PBU) in u32; LN overlay needs 128*PA floats
#define DSMEM ((128*PAU + 2*256*PBU) * 4)   /* 141,312 B >= 133,120 LN */

// ---------------- K23: e-proj + attn + softmax-agg + edge_out + LN4 --------
__global__ void __launch_bounds__(512, 1) k23(
    const float* __restrict__ y, const float* __restrict__ be,
    const float* __restrict__ boe,
    const float* __restrict__ ln4_s, const float* __restrict__ ln4_b)
{
    extern __shared__ __align__(16) char dsm[];
    uint32_t* sA  = (uint32_t*)dsm;
    uint32_t* sB0 = sA + 128 * PAU;
    uint32_t* sB1 = sB0 + 256 * PBU;
    float* ln = (float*)dsm;
    __shared__ float s_q[CC], s_bb[CC], s_b2[CC];

    int t = threadIdx.x, lane = t & 31, wid = t >> 5;
    int m0 = (wid & 3) * 32, n0 = (wid >> 2) * 64;
    int g = lane >> 2, tig = lane & 3;
    int tile = blockIdx.x;
    size_t base = (size_t)tile * 128;
    int krow = (tile >> 7) << 7;

    if (t < CC) {
        s_bb[t] = be[t];
        s_b2[t] = boe[t];
        s_q[t]  = g_q[(size_t)tile*CC + t] * 0.17677669529663687f;  // 1/sqrt(32)
    }
    stageAh(sA, y, base, CC, 0, t);
    uint4 pB[4];
    ldgBh(pB, g_WeTh, CC, 0, t);
    __syncthreads();                 // sA + s_* ready

    // ---- GEMM1: e = y @ We + be (double-buffered sB, 1 sync/chunk) --------
    float acc[2][8][4];
    initacc(acc, s_bb, n0, tig);
#pragma unroll 1
    for (int kc = 0; kc < 4; kc++) {
        stsBh((kc & 1) ? sB1 : sB0, pB, t);
        if (kc < 3) ldgBh(pB, g_WeTh, CC, (kc + 1) * 64, t);
        __syncthreads();
        gemm64h(sA + kc * 32, (kc & 1) ? sB1 : sB0, acc, m0, n0, g, tig);
    }
    ldgBh(pB, g_WoeTh, CC, 0, t);    // prefetch GEMM2 chunk0
    __syncthreads();                 // all warps done reading sA

    // ---- epilogue1: attn = q*k/sqrt(dk)*(e+1)*e -> half2 into sA ----------
#pragma unroll
    for (int mf = 0; mf < 2; mf++)
#pragma unroll
        for (int nf = 0; nf < 8; nf++) {
            int r = m0 + mf * 16 + g;
            int c = n0 + nf * 8 + 2 * tig;
#pragma unroll
            for (int h = 0; h < 2; h++) {
                int rr = r + 8 * h;
                float e0 = acc[mf][nf][2*h], e1 = acc[mf][nf][2*h+1];
                float2 kv = *(const float2*)(g_k + (size_t)(krow + rr) * CC + c);
                float a0 = s_q[c]   * kv.x * (e0 + 1.f) * e0;
                float a1 = s_q[c+1] * kv.y * (e1 + 1.f) * e1;
                sA[rr * PAU + (c >> 1)] = f2h2(a0, a1);
            }
        }
    __syncthreads();                 // attn tile visible

    // ---- fused softmax over j + V aggregation (tile-local) ----------------
    {
        float* red = (float*)sB0;    // 1536 floats of partials
        int c = t & 255, half = t >> 8;
        const float* vp = g_v + (size_t)(krow + half * 64) * CC + c;
        float m = -3.4e38f, s = 0.f, a = 0.f;
#pragma unroll 4
        for (int j = 0; j < 64; j++) {
            uint32_t u = sA[(half * 64 + j) * PAU + (c >> 1)];
            float2 h2 = __half22float2(*(const __half2*)&u);
            float av = (c & 1) ? h2.y : h2.x;
            float nm = fmaxf(m, av);
            float corr = __expf(m - nm);
            float p = __expf(av - nm);
            s = s * corr + p;
            a = a * corr + p * vp[(size_t)j * CC];
            m = nm;
        }
        red[half * 256 + c]        = m;
        red[512 + half * 256 + c]  = s;
        red[1024 + half * 256 + c] = a;
        __syncthreads();
        if (t < 256) {
            float m0_ = red[c],       m1_ = red[256 + c];
            float s0  = red[512 + c], s1  = red[768 + c];
            float a0  = red[1024 + c], a1 = red[1280 + c];
            float mm = fmaxf(m0_, m1_);
            float e0 = __expf(m0_ - mm), e1 = __expf(m1_ - mm);
            g_agg[(size_t)tile * CC + c] = (a0 * e0 + a1 * e1) / (s0 * e0 + s1 * e1);
        }
    }
    __syncthreads();                 // red reads done; sB free

    // ---- GEMM2: edge_out = attn @ Woe + boe -------------------------------
    initacc(acc, s_b2, n0, tig);
#pragma unroll 1
    for (int kc = 0; kc < 4; kc++) {
        stsBh((kc & 1) ? sB1 : sB0, pB, t);
        if (kc < 3) ldgBh(pB, g_WoeTh, CC, (kc + 1) * 64, t);
        __syncthreads();
        gemm64h(sA + kc * 32, (kc & 1) ? sB1 : sB0, acc, m0, n0, g, tig);
    }
    __syncthreads();                 // gemm reads done; ln overlay safe

    // ---- epilogue2: + y residual -> ln buffer -> LN4 -> g_y2 --------------
#pragma unroll
    for (int mf = 0; mf < 2; mf++)
#pragma unroll
        for (int nf = 0; nf < 8; nf++) {
            int r = m0 + mf * 16 + g;
            int c = n0 + nf * 8 + 2 * tig;
#pragma unroll
            for (int h = 0; h < 2; h++) {
                int rr = r + 8 * h;
                float2 yv = *(const float2*)(y + (base + rr) * CC + c);
                float2 o;
                o.x = acc[mf][nf][2*h]   + yv.x;
                o.y = acc[mf][nf][2*h+1] + yv.y;
                *(float2*)(ln + rr * PA + c) = o;
            }
        }
    __syncthreads();

    ln_rows128(ln, g_y2, base, ln4_s, ln4_b, t);
}

// ---------------- K5: node out proj + LN3 + MLP + LN5 ----------------------
__global__ void __launch_bounds__(256) k5_node_mlp(
    const float* __restrict__ Won, const float* __restrict__ bon,
    const float* __restrict__ w1, const float* __restrict__ b1,
    const float* __restrict__ w2, const float* __restrict__ b2,
    const float* __restrict__ ln3_s, const float* __restrict__ ln3_b,
    const float* __restrict__ ln5_s, const float* __restrict__ ln5_b,
    float* __restrict__ xout)
{
    __shared__ __align__(16) float sagg[CC];
    __shared__ __align__(16) float sx2[CC];
    __shared__ __align__(16) float shid[HID];
    __shared__ float sred[8];
    int r = blockIdx.x, t = threadIdx.x;

    sagg[t] = g_agg[r*CC + t];
    __syncthreads();

    float no = bon[t];
    const float4* sa4 = (const float4*)sagg;
#pragma unroll 1
    for (int k4 = 0; k4 < CC/4; k4++) {
        float4 av = sa4[k4]; int kk = 4*k4;
        no = fmaf(av.x, Won[(kk+0)*CC+t], no);
        no = fmaf(av.y, Won[(kk+1)*CC+t], no);
        no = fmaf(av.z, Won[(kk+2)*CC+t], no);
        no = fmaf(av.w, Won[(kk+3)*CC+t], no);
    }
    float pre = g_x1[r*CC + t] + no;

    float mean = blockSum(pre, sred, t) * (1.f/CC);
    float d = pre - mean;
    float var = blockSum(d*d, sred, t) * (1.f/CC);
    float x2 = d * rsqrtf(var + EPSF) * ln3_s[t] + ln3_b[t];
    sx2[t] = x2;
    __syncthreads();

    const float4* sx24 = (const float4*)sx2;
#pragma unroll 1
    for (int hb = 0; hb < 4; hb++) {
        int h = hb*CC + t;
        float a = b1[h];
#pragma unroll 1
        for (int k4 = 0; k4 < CC/4; k4++) {
            float4 xv = sx24[k4]; int kk = 4*k4;
            a = fmaf(xv.x, w1[(kk+0)*HID+h], a);
            a = fmaf(xv.y, w1[(kk+1)*HID+h], a);
            a = fmaf(xv.z, w1[(kk+2)*HID+h], a);
            a = fmaf(xv.w, w1[(kk+3)*HID+h], a);
        }
        shid[h] = fmaxf(a, 0.f);
    }
    __syncthreads();

    float o = b2[t];
    const float4* sh4 = (const float4*)shid;
#pragma unroll 1
    for (int k4 = 0; k4 < HID/4; k4++) {
        float4 hv = sh4[k4]; int kk = 4*k4;
        o = fmaf(hv.x, w2[(kk+0)*CC+t], o);
        o = fmaf(hv.y, w2[(kk+1)*CC+t], o);
        o = fmaf(hv.z, w2[(kk+2)*CC+t], o);
        o = fmaf(hv.w, w2[(kk+3)*CC+t], o);
    }
    float pre2 = x2 + o;
    float mean2 = blockSum(pre2, sred, t) * (1.f/CC);
    float d2 = pre2 - mean2;
    float var2 = blockSum(d2*d2, sred, t) * (1.f/CC);
    xout[r*CC + t] = d2 * rsqrtf(var2 + EPSF) * ln5_s[t] + ln5_b[t];
}

// ---------------- K6f: fused edge MLP + LN6 (fp16 MMA, half hid) -----------
__global__ void __launch_bounds__(512, 1) k6f(
    const float* __restrict__ b1, const float* __restrict__ b2,
    const float* __restrict__ ln6_s, const float* __restrict__ ln6_b,
    float* __restrict__ yout)
{
    extern __shared__ __align__(16) char dsm[];
    uint32_t* sA  = (uint32_t*)dsm;
    uint32_t* sB0 = sA + 128 * PAU;
    uint32_t* sB1 = sB0 + 256 * PBU;
    float* ln = (float*)dsm;
    __shared__ float sb1[HID];
    __shared__ float sb2[CC];

    int t = threadIdx.x, lane = t & 31, wid = t >> 5;
    int m0 = (wid & 3) * 32, n0 = (wid >> 2) * 64;
    int g = lane >> 2, tig = lane & 3;
    int tile = blockIdx.x;
    size_t base = (size_t)tile * 128;

    sb1[t] = b1[t]; sb1[t + 512] = b1[t + 512];
    if (t < CC) sb2[t] = b2[t];
    stageAh(sA, g_y2, base, CC, 0, t);
    uint4 pB[4];
    ldgBh(pB, g_w1Th, CC, 0, t);
    __syncthreads();

    // ======== phase 1: hid = relu(y2 @ w1 + b1), 4 N-chunks ================
#pragma unroll 1
    for (int nc = 0; nc < 4; nc++) {
        float acc[2][8][4];
        initacc(acc, sb1 + nc * CC, n0, tig);
#pragma unroll 1
        for (int kc = 0; kc < 4; kc++) {
            int cgl = nc * 4 + kc;
            stsBh((cgl & 1) ? sB1 : sB0, pB, t);
            int nxt = cgl + 1;
            if (nxt < 16)
                ldgBh(pB, g_w1Th + (size_t)(nxt >> 2) * 256 * CC, CC,
                      (nxt & 3) * 64, t);
            __syncthreads();
            gemm64h(sA + kc * 32, (cgl & 1) ? sB1 : sB0, acc, m0, n0, g, tig);
        }

        // epilogue: relu -> half2 -> g_hidh
#pragma unroll
        for (int mf = 0; mf < 2; mf++)
#pragma unroll
            for (int nf = 0; nf < 8; nf++) {
                int r = m0 + mf * 16 + g;
                int c = nc * CC + n0 + nf * 8 + 2 * tig;
#pragma unroll
                for (int h = 0; h < 2; h++) {
                    int rr = r + 8 * h;
                    float o0 = fmaxf(acc[mf][nf][2*h],   0.f);
                    float o1 = fmaxf(acc[mf][nf][2*h+1], 0.f);
                    g_hidh[((base + rr) * HID + c) >> 1] = f2h2(o0, o1);
                }
            }
    }

    // ======== phase 2: out = hid @ w2 + b2 + y2 ; LN6 ======================
    ldgBh(pB, g_w2Th, HID, 0, t);
    float acc[2][8][4];
    initacc(acc, sb2, n0, tig);

#pragma unroll 1
    for (int cc = 0; cc < 16; cc++) {
        if ((cc & 3) == 0) {
            __syncthreads();         // prior gemm done with sA; hid visible
            stageAcpy(sA, g_hidh, base, (cc >> 2) * 128, t);
        }
        stsBh((cc & 1) ? sB1 : sB0, pB, t);
        if (cc < 15) ldgBh(pB, g_w2Th, HID, (cc + 1) * 64, t);
        __syncthreads();             // sA (if restaged) + sB ready
        gemm64h(sA + (cc & 3) * 32, (cc & 1) ? sB1 : sB0, acc, m0, n0, g, tig);
    }
    __syncthreads();                 // gemm reads done; ln overlay safe

#pragma unroll
    for (int mf = 0; mf < 2; mf++)
#pragma unroll
        for (int nf = 0; nf < 8; nf++) {
            int r = m0 + mf * 16 + g;
            int c = n0 + nf * 8 + 2 * tig;
#pragma unroll
            for (int h = 0; h < 2; h++) {
                int rr = r + 8 * h;
                float2 yv = *(const float2*)(g_y2 + (base + rr) * CC + c);
                float2 o;
                o.x = acc[mf][nf][2*h]   + yv.x;
                o.y = acc[mf][nf][2*h+1] + yv.y;
                *(float2*)(ln + rr * PA + c) = o;
            }
        }
    __syncthreads();

    ln_rows128(ln, yout, base, ln6_s, ln6_b, t);
}

// ---------------- launch ---------------------------------------------------
extern "C" void kernel_launch(void* const* d_in, const int* in_sizes, int n_in,
                              void* d_out, int out_size)
{
    const float* x   = (const float*)d_in[0];
    const float* y   = (const float*)d_in[1];
    const float* Wq  = (const float*)d_in[2];
    const float* bq  = (const float*)d_in[3];
    const float* Wk  = (const float*)d_in[4];
    const float* bk  = (const float*)d_in[5];
    const float* Wv  = (const float*)d_in[6];
    const float* bv  = (const float*)d_in[7];
    const float* We  = (const float*)d_in[8];
    const float* be  = (const float*)d_in[9];
    const float* Woe = (const float*)d_in[10];
    const float* boe = (const float*)d_in[11];
    const float* Won = (const float*)d_in[12];
    const float* bon = (const float*)d_in[13];
    const float* m1w1 = (const float*)d_in[14];
    const float* m1b1 = (const float*)d_in[15];
    const float* m1w2 = (const float*)d_in[16];
    const float* m1b2 = (const float*)d_in[17];
    const float* m2w1 = (const float*)d_in[18];
    const float* m2b1 = (const float*)d_in[19];
    const float* m2w2 = (const float*)d_in[20];
    const float* m2b2 = (const float*)d_in[21];
    const float* ln1s = (const float*)d_in[22];
    const float* ln1b = (const float*)d_in[23];
    const float* ln3s = (const float*)d_in[24];
    const float* ln3b = (const float*)d_in[25];
    const float* ln4s = (const float*)d_in[26];
    const float* ln4b = (const float*)d_in[27];
    const float* ln5s = (const float*)d_in[28];
    const float* ln5b = (const float*)d_in[29];
    const float* ln6s = (const float*)d_in[30];
    const float* ln6b = (const float*)d_in[31];

    float* xout = (float*)d_out;                   // (8,128,256)
    float* yout = (float*)d_out + ROWS*CC;         // (8,128,128,256)

    cudaFuncSetAttribute(k23, cudaFuncAttributeMaxDynamicSharedMemorySize, DSMEM);
    cudaFuncSetAttribute(k6f, cudaFuncAttributeMaxDynamicSharedMemorySize, DSMEM);

    ktrans<<<dim3(8, 8),  dim3(32, 8)>>>(We,   CC,  CC,  0);
    ktrans<<<dim3(8, 8),  dim3(32, 8)>>>(Woe,  CC,  CC,  1);
    ktrans<<<dim3(32, 8), dim3(32, 8)>>>(m2w1, CC,  HID, 2);
    ktrans<<<dim3(8, 32), dim3(32, 8)>>>(m2w2, HID, CC,  3);

    k1_node_qkv<<<ROWS, 256>>>(x, Wq, bq, Wk, bk, Wv, bv, ln1s, ln1b);
    k23<<<ROWS, 512, DSMEM>>>(y, be, boe, ln4s, ln4b);
    k5_node_mlp<<<ROWS, 256>>>(Won, bon, m1w1, m1b1, m1w2, m1b2,
                               ln3s, ln3b, ln5s, ln5b, xout);
    k6f<<<ROWS, 512, DSMEM>>>(m2b1, m2b2, ln6s, ln6b, yout);
}